// round 4
// baseline (speedup 1.0000x reference)
#include <cuda_runtime.h>

#define Bc 4
#define Sc 2048
#define Dc 1024
#define Hc 16
#define HDc 64
#define Fc 4096
#define Ec 8
#define Kc 2
#define Tc (Bc*Sc)   /* 8192 */

// ---------------- scratch (static device globals; no allocation) ----------------
__device__ float g_Q[Tc*Dc];
__device__ float g_Kb[Tc*Dc];
__device__ float g_Vb[Tc*Dc];
__device__ float g_AO[Tc*Dc];
__device__ float g_P[Tc*Dc];
__device__ float g_X1[Tc*Dc];
__device__ float g_moe[Tc*Dc];
__device__ float g_H[(size_t)Tc*Fc];
__device__ int   g_cnt[Ec];
__device__ int   g_eidx[Ec*Tc];
__device__ float g_ewgt[Ec*Tc];
__device__ float g_scores[Tc*Ec];

__device__ __forceinline__ float gelu_f(float v) {
    return 0.5f * v * (1.0f + erff(v * 0.70710678118654752f));
}

// ---------------- generic tiled SGEMM: C = op(A@B + bias) ----------------
// MODE 0: store (bias add)            — projections
// MODE 1: store gelu(acc+bias)        — expert W1
// MODE 2: C[rowidx[m]] += w[m]*(acc+bias) — expert W2 scatter-accumulate
// GATHER: A row index indirected through rowidx
// Mcnt: device-side row count (dynamic M); nullptr -> use M
template<int MODE, bool GATHER>
__global__ void __launch_bounds__(256) sgemm_kernel(
    const float* __restrict__ A, const float* __restrict__ Bm,
    const float* __restrict__ bias, float* __restrict__ C,
    int M, int N, int Kd,
    const int* __restrict__ rowidx, const float* __restrict__ roww,
    const int* __restrict__ Mcnt)
{
    int Meff = Mcnt ? *Mcnt : M;
    int m0 = blockIdx.y * 128;
    if (m0 >= Meff) return;
    int n0 = blockIdx.x * 128;

    __shared__ float As[16][128];
    __shared__ float Bs[16][128];

    int tid = threadIdx.x;
    int tx = tid & 15, ty = tid >> 4;

    float acc[8][8];
#pragma unroll
    for (int i = 0; i < 8; i++)
#pragma unroll
        for (int j = 0; j < 8; j++) acc[i][j] = 0.f;

    int lr = tid >> 2;        // 0..63 (A tile row)
    int lk = (tid & 3) * 4;   // k offset within 16
    int r0 = m0 + lr, r1 = m0 + lr + 64;
    bool v0 = r0 < Meff, v1 = r1 < Meff;
    int ga0 = 0, ga1 = 0;
    if (v0) ga0 = GATHER ? rowidx[r0] : r0;
    if (v1) ga1 = GATHER ? rowidx[r1] : r1;

    int bk = tid >> 5;        // 0..7 (B tile k-row)
    int bn = (tid & 31) * 4;  // B tile col

    for (int k0 = 0; k0 < Kd; k0 += 16) {
        float4 a0 = make_float4(0.f,0.f,0.f,0.f), a1 = make_float4(0.f,0.f,0.f,0.f);
        if (v0) a0 = *(const float4*)(A + (size_t)ga0 * Kd + k0 + lk);
        if (v1) a1 = *(const float4*)(A + (size_t)ga1 * Kd + k0 + lk);
        float4 b0 = *(const float4*)(Bm + (size_t)(k0 + bk)     * N + n0 + bn);
        float4 b1 = *(const float4*)(Bm + (size_t)(k0 + bk + 8) * N + n0 + bn);
        __syncthreads();
        As[lk+0][lr] = a0.x; As[lk+1][lr] = a0.y; As[lk+2][lr] = a0.z; As[lk+3][lr] = a0.w;
        As[lk+0][lr+64] = a1.x; As[lk+1][lr+64] = a1.y; As[lk+2][lr+64] = a1.z; As[lk+3][lr+64] = a1.w;
        *(float4*)&Bs[bk][bn]     = b0;
        *(float4*)&Bs[bk + 8][bn] = b1;
        __syncthreads();
#pragma unroll
        for (int kk = 0; kk < 16; kk++) {
            float a[8], b[8];
            *(float4*)&a[0] = *(const float4*)&As[kk][ty * 8];
            *(float4*)&a[4] = *(const float4*)&As[kk][ty * 8 + 4];
            *(float4*)&b[0] = *(const float4*)&Bs[kk][tx * 8];
            *(float4*)&b[4] = *(const float4*)&Bs[kk][tx * 8 + 4];
#pragma unroll
            for (int i = 0; i < 8; i++)
#pragma unroll
                for (int j = 0; j < 8; j++)
                    acc[i][j] = fmaf(a[i], b[j], acc[i][j]);
        }
    }

#pragma unroll
    for (int i = 0; i < 8; i++) {
        int m = m0 + ty * 8 + i;
        if (m >= Meff) break;
        int crow = m;
        float w = 1.f;
        if (MODE == 2) { crow = rowidx[m]; w = roww[m]; }
        float* cp = C + (size_t)crow * N + n0 + tx * 8;
        const float* bp = bias + n0 + tx * 8;
#pragma unroll
        for (int j = 0; j < 8; j++) {
            float v = acc[i][j] + bp[j];
            if (MODE == 1) v = gelu_f(v);
            if (MODE == 2) cp[j] += w * v;
            else           cp[j] = v;
        }
    }
}

// ---------------- flash attention, fp32, 64q x 64kv tiles ----------------
__global__ void __launch_bounds__(256) attn_kernel(
    const float* __restrict__ Q, const float* __restrict__ Kin,
    const float* __restrict__ Vin, float* __restrict__ Out)
{
    __shared__ float Ks[64][65];
    __shared__ float Vs[64][64];
    int bh = blockIdx.y;
    int b = bh >> 4, h = bh & 15;
    int q0 = blockIdx.x * 64;
    int tid = threadIdx.x;
    int lane = tid & 31;
    int r = tid >> 2, quad = tid & 3;
    int dq = quad * 16;
    int srcbase = lane & ~3;
    const unsigned fullm = 0xffffffffu;
    size_t base = (size_t)(b * Sc) * Dc + h * 64;

    float qf[16];
    {
        const float* qp = Q + base + (size_t)(q0 + r) * Dc + dq;
#pragma unroll
        for (int j = 0; j < 16; j += 4) {
            float4 t4 = *(const float4*)(qp + j);
            qf[j] = t4.x; qf[j+1] = t4.y; qf[j+2] = t4.z; qf[j+3] = t4.w;
        }
    }
    float mx = -1e30f, l = 0.f;
    float o[16];
#pragma unroll
    for (int j = 0; j < 16; j++) o[j] = 0.f;

    for (int kv0 = 0; kv0 < Sc; kv0 += 64) {
        const float* kp = Kin + base + (size_t)(kv0 + r) * Dc + dq;
        const float* vp = Vin + base + (size_t)(kv0 + r) * Dc + dq;
        __syncthreads();
#pragma unroll
        for (int j = 0; j < 16; j += 4) {
            float4 k4 = *(const float4*)(kp + j);
            Ks[r][dq+j] = k4.x; Ks[r][dq+j+1] = k4.y; Ks[r][dq+j+2] = k4.z; Ks[r][dq+j+3] = k4.w;
            float4 v4 = *(const float4*)(vp + j);
            *(float4*)&Vs[r][dq + j] = v4;
        }
        __syncthreads();

        float s[16];
#pragma unroll
        for (int i = 0; i < 16; i++) s[i] = 0.f;
        for (int dqd = 0; dqd < 4; dqd++) {
#pragma unroll
            for (int ii = 0; ii < 16; ii++) {
                float qv = __shfl_sync(fullm, qf[ii], srcbase | dqd, 32);
                int d = dqd * 16 + ii;
#pragma unroll
                for (int i = 0; i < 16; i++)
                    s[i] = fmaf(qv, Ks[dq + i][d], s[i]);
            }
        }

        float tmax = -1e30f;
#pragma unroll
        for (int i = 0; i < 16; i++) { s[i] *= 0.125f; tmax = fmaxf(tmax, s[i]); }
        tmax = fmaxf(tmax, __shfl_xor_sync(fullm, tmax, 1));
        tmax = fmaxf(tmax, __shfl_xor_sync(fullm, tmax, 2));
        float mnew = fmaxf(mx, tmax);
        float alpha = __expf(mx - mnew);
        float rsum = 0.f;
#pragma unroll
        for (int i = 0; i < 16; i++) { s[i] = __expf(s[i] - mnew); rsum += s[i]; }
        rsum += __shfl_xor_sync(fullm, rsum, 1);
        rsum += __shfl_xor_sync(fullm, rsum, 2);
        l = l * alpha + rsum;
        mx = mnew;
#pragma unroll
        for (int j = 0; j < 16; j++) o[j] *= alpha;

        for (int kq = 0; kq < 4; kq++) {
#pragma unroll
            for (int ii = 0; ii < 16; ii++) {
                float pv = __shfl_sync(fullm, s[ii], srcbase | kq, 32);
                int k = kq * 16 + ii;
#pragma unroll
                for (int j = 0; j < 16; j += 4) {
                    float4 v4 = *(const float4*)&Vs[k][dq + j];
                    o[j]   = fmaf(pv, v4.x, o[j]);
                    o[j+1] = fmaf(pv, v4.y, o[j+1]);
                    o[j+2] = fmaf(pv, v4.z, o[j+2]);
                    o[j+3] = fmaf(pv, v4.w, o[j+3]);
                }
            }
        }
    }

    float inv = 1.f / l;
    float* op = Out + base + (size_t)(q0 + r) * Dc + dq;
#pragma unroll
    for (int j = 0; j < 16; j++) op[j] = o[j] * inv;
}

// ---------------- residual + layernorm ----------------
__global__ void __launch_bounds__(256) add_ln_kernel(
    const float* __restrict__ xin, const float* __restrict__ res,
    const float* __restrict__ g, const float* __restrict__ bta,
    float* __restrict__ out)
{
    int t = blockIdx.x;
    int tid = threadIdx.x;
    const float4 xv = ((const float4*)(xin + (size_t)t * Dc))[tid];
    const float4 rv = ((const float4*)(res + (size_t)t * Dc))[tid];
    float v[4] = {xv.x + rv.x, xv.y + rv.y, xv.z + rv.z, xv.w + rv.w};
    float s  = v[0] + v[1] + v[2] + v[3];
    float sq = v[0]*v[0] + v[1]*v[1] + v[2]*v[2] + v[3]*v[3];
#pragma unroll
    for (int off = 16; off; off >>= 1) {
        s  += __shfl_xor_sync(0xffffffffu, s, off);
        sq += __shfl_xor_sync(0xffffffffu, sq, off);
    }
    __shared__ float ss[8], qq[8];
    __shared__ float smu, srstd;
    int wid = tid >> 5;
    if ((tid & 31) == 0) { ss[wid] = s; qq[wid] = sq; }
    __syncthreads();
    if (tid == 0) {
        float ts = 0.f, tq = 0.f;
#pragma unroll
        for (int i = 0; i < 8; i++) { ts += ss[i]; tq += qq[i]; }
        float mu = ts / (float)Dc;
        float var = tq / (float)Dc - mu * mu;
        smu = mu; srstd = rsqrtf(var + 1e-5f);
    }
    __syncthreads();
    float mu = smu, rstd = srstd;
    float4 g4 = ((const float4*)g)[tid];
    float4 b4 = ((const float4*)bta)[tid];
    float4 o4;
    o4.x = (v[0]-mu)*rstd*g4.x + b4.x;
    o4.y = (v[1]-mu)*rstd*g4.y + b4.y;
    o4.z = (v[2]-mu)*rstd*g4.z + b4.z;
    o4.w = (v[3]-mu)*rstd*g4.w + b4.w;
    ((float4*)(out + (size_t)t * Dc))[tid] = o4;
}

// ---------------- gate: logits, softmax, top-2, routing lists ----------------
__global__ void __launch_bounds__(256) gate_kernel(
    const float* __restrict__ x1, const float* __restrict__ gW,
    const float* __restrict__ gb)
{
    int t = blockIdx.x;
    int tid = threadIdx.x;
    float part[Ec];
#pragma unroll
    for (int e = 0; e < Ec; e++) part[e] = 0.f;
    const float* xr = x1 + (size_t)t * Dc;
    for (int d = tid; d < Dc; d += 256) {
        float xv = xr[d];
        const float* wr = gW + d * Ec;
#pragma unroll
        for (int e = 0; e < Ec; e++) part[e] += xv * wr[e];
    }
    __shared__ float sm[Ec][264];
#pragma unroll
    for (int e = 0; e < Ec; e++) sm[e][tid] = part[e];
    __syncthreads();
    for (int off = 128; off; off >>= 1) {
        if (tid < off) {
#pragma unroll
            for (int e = 0; e < Ec; e++) sm[e][tid] += sm[e][tid + off];
        }
        __syncthreads();
    }
    if (tid == 0) {
        float lg[Ec], sc[Ec];
        float m = -1e30f;
#pragma unroll
        for (int e = 0; e < Ec; e++) { lg[e] = sm[e][0] + gb[e]; m = fmaxf(m, lg[e]); }
        float sum = 0.f;
#pragma unroll
        for (int e = 0; e < Ec; e++) { sc[e] = expf(lg[e] - m); sum += sc[e]; }
        float inv = 1.f / sum;
#pragma unroll
        for (int e = 0; e < Ec; e++) { sc[e] *= inv; g_scores[t * Ec + e] = sc[e]; }
        int a1 = 0;
#pragma unroll
        for (int e = 1; e < Ec; e++) if (sc[e] > sc[a1]) a1 = e;
        int a2 = (a1 == 0) ? 1 : 0;
#pragma unroll
        for (int e = 0; e < Ec; e++) if (e != a1 && sc[e] > sc[a2]) a2 = e;
        float ws = sc[a1] + sc[a2];
        float w1 = sc[a1] / ws, w2 = sc[a2] / ws;
        int p1 = atomicAdd(&g_cnt[a1], 1);
        g_eidx[a1 * Tc + p1] = t; g_ewgt[a1 * Tc + p1] = w1;
        int p2 = atomicAdd(&g_cnt[a2], 1);
        g_eidx[a2 * Tc + p2] = t; g_ewgt[a2 * Tc + p2] = w2;
    }
}

// ---------------- aux loss (deterministic fixed-order reduction) ----------------
__global__ void __launch_bounds__(256) aux_kernel(float* __restrict__ out)
{
    int tid = threadIdx.x;
    float part[Ec];
#pragma unroll
    for (int e = 0; e < Ec; e++) part[e] = 0.f;
    for (int t = tid; t < Tc; t += 256) {
#pragma unroll
        for (int e = 0; e < Ec; e++) part[e] += g_scores[t * Ec + e];
    }
    __shared__ float sm[Ec][264];
#pragma unroll
    for (int e = 0; e < Ec; e++) sm[e][tid] = part[e];
    __syncthreads();
    for (int off = 128; off; off >>= 1) {
        if (tid < off) {
#pragma unroll
            for (int e = 0; e < Ec; e++) sm[e][tid] += sm[e][tid + off];
        }
        __syncthreads();
    }
    if (tid == 0) {
        float aux = 0.f;
#pragma unroll
        for (int e = 0; e < Ec; e++) {
            float ef = (float)g_cnt[e] / (float)(Tc * Kc);
            float rw = sm[e][0] / (float)Tc;
            aux += ef * rw;
        }
        out[0] = aux * (float)Ec;
    }
}

// ---------------- state reset (graph replays need clean state) ----------------
__global__ void zero_cnt_kernel() {
    if (threadIdx.x < Ec) g_cnt[threadIdx.x] = 0;
}
__global__ void zero_moe_kernel() {
    size_t i = ((size_t)blockIdx.x * 256 + threadIdx.x) * 4;
    *(float4*)(g_moe + i) = make_float4(0.f, 0.f, 0.f, 0.f);
}

// ---------------- launch ----------------
extern "C" void kernel_launch(void* const* d_in, const int* in_sizes, int n_in,
                              void* d_out, int out_size)
{
    (void)in_sizes; (void)n_in; (void)out_size;
    const float* x     = (const float*)d_in[0];
    const float* Wq    = (const float*)d_in[1];
    const float* bq    = (const float*)d_in[2];
    const float* Wk    = (const float*)d_in[3];
    const float* bk    = (const float*)d_in[4];
    const float* Wv    = (const float*)d_in[5];
    const float* bv    = (const float*)d_in[6];
    const float* Wo    = (const float*)d_in[7];
    const float* bo    = (const float*)d_in[8];
    const float* g1    = (const float*)d_in[9];
    const float* beta1 = (const float*)d_in[10];
    const float* gateW = (const float*)d_in[11];
    const float* gateb = (const float*)d_in[12];
    const float* eW1   = (const float*)d_in[13];
    const float* eb1   = (const float*)d_in[14];
    const float* eW2   = (const float*)d_in[15];
    const float* eb2   = (const float*)d_in[16];
    const float* g2    = (const float*)d_in[17];
    const float* beta2 = (const float*)d_in[18];
    float* out = (float*)d_out;

    float *pQ, *pK, *pV, *pAO, *pP, *pX1, *pMoe, *pH, *pWgt;
    int *pCnt, *pIdx;
    cudaGetSymbolAddress((void**)&pQ,   g_Q);
    cudaGetSymbolAddress((void**)&pK,   g_Kb);
    cudaGetSymbolAddress((void**)&pV,   g_Vb);
    cudaGetSymbolAddress((void**)&pAO,  g_AO);
    cudaGetSymbolAddress((void**)&pP,   g_P);
    cudaGetSymbolAddress((void**)&pX1,  g_X1);
    cudaGetSymbolAddress((void**)&pMoe, g_moe);
    cudaGetSymbolAddress((void**)&pH,   g_H);
    cudaGetSymbolAddress((void**)&pCnt, g_cnt);
    cudaGetSymbolAddress((void**)&pIdx, g_eidx);
    cudaGetSymbolAddress((void**)&pWgt, g_ewgt);

    zero_cnt_kernel<<<1, 32>>>();
    zero_moe_kernel<<<(Tc * Dc) / 1024, 256>>>();

    dim3 gD(Dc / 128, Tc / 128);   // (8, 64)
    sgemm_kernel<0,false><<<gD, 256>>>(x, Wq, bq, pQ, Tc, Dc, Dc, nullptr, nullptr, nullptr);
    sgemm_kernel<0,false><<<gD, 256>>>(x, Wk, bk, pK, Tc, Dc, Dc, nullptr, nullptr, nullptr);
    sgemm_kernel<0,false><<<gD, 256>>>(x, Wv, bv, pV, Tc, Dc, Dc, nullptr, nullptr, nullptr);

    attn_kernel<<<dim3(Sc / 64, Bc * Hc), 256>>>(pQ, pK, pV, pAO);

    sgemm_kernel<0,false><<<gD, 256>>>(pAO, Wo, bo, pP, Tc, Dc, Dc, nullptr, nullptr, nullptr);
    add_ln_kernel<<<Tc, 256>>>(x, pP, g1, beta1, pX1);

    gate_kernel<<<Tc, 256>>>(pX1, gateW, gateb);

    dim3 gF(Fc / 128, Tc / 128);   // (32, 64)
    for (int e = 0; e < Ec; e++) {
        sgemm_kernel<1,true><<<gF, 256>>>(pX1, eW1 + (size_t)e * Dc * Fc, eb1 + e * Fc,
                                          pH, Tc, Fc, Dc,
                                          pIdx + e * Tc, nullptr, pCnt + e);
        sgemm_kernel<2,false><<<gD, 256>>>(pH, eW2 + (size_t)e * Fc * Dc, eb2 + e * Dc,
                                           pMoe, Tc, Dc, Fc,
                                           pIdx + e * Tc, pWgt + e * Tc, pCnt + e);
    }

    add_ln_kernel<<<Tc, 256>>>(pX1, pMoe, g2, beta2, out);
    aux_kernel<<<1, 256>>>(out + (size_t)Tc * Dc);
}

// round 5
// speedup vs baseline: 3.5896x; 3.5896x over previous
#include <cuda_runtime.h>
#include <cstdint>

#define Bc 4
#define Sc 2048
#define Dc 1024
#define Hc 16
#define HDc 64
#define Fc 4096
#define Ec 8
#define Kc 2
#define Tc (Bc*Sc)   /* 8192 */

// ---------------- scratch (static device globals; no allocation) ----------------
__device__ float g_Q[Tc*Dc];
__device__ float g_Kb[Tc*Dc];
__device__ float g_Vb[Tc*Dc];
__device__ float g_AO[Tc*Dc];
__device__ float g_P[Tc*Dc];
__device__ float g_X1[Tc*Dc];
__device__ float g_moe[Tc*Dc];
__device__ float g_H[(size_t)Tc*Fc];
__device__ int   g_cnt[Ec];
__device__ int   g_eidx[Ec*Tc];
__device__ float g_ewgt[Ec*Tc];
__device__ float g_scores[Tc*Ec];

__device__ __forceinline__ float gelu_f(float v) {
    return 0.5f * v * (1.0f + erff(v * 0.70710678118654752f));
}

// tf32 convert (round-to-nearest)
__device__ __forceinline__ uint32_t f2tf(float f) {
    uint32_t u; asm("cvt.rna.tf32.f32 %0, %1;" : "=r"(u) : "f"(f)); return u;
}

// D += A(16x8,row) * B(8x8,col) ; fp32 accumulate
__device__ __forceinline__ void mma8(float4& d, const uint32_t* a, const uint32_t* b) {
    asm volatile(
        "mma.sync.aligned.m16n8k8.row.col.f32.tf32.tf32.f32 "
        "{%0,%1,%2,%3}, {%4,%5,%6,%7}, {%8,%9}, {%0,%1,%2,%3};\n"
        : "+f"(d.x), "+f"(d.y), "+f"(d.z), "+f"(d.w)
        : "r"(a[0]), "r"(a[1]), "r"(a[2]), "r"(a[3]), "r"(b[0]), "r"(b[1]));
}

// ---------------- tf32 tensor-core GEMM: C = op(A@B + bias) ----------------
// Tile 128x128, Ktile 16, 8 warps (2x4), warp tile 64x32.
// MODE 0: store (bias add)            — projections
// MODE 1: store gelu(acc+bias)        — expert W1
// MODE 2: C[rowidx[m]] += w[m]*(acc+bias) — expert W2 scatter-accumulate
// GATHER: A row index indirected through rowidx; Mcnt: device-side dynamic M
template<int MODE, bool GATHER>
__global__ void __launch_bounds__(256) gemm_tc(
    const float* __restrict__ A, const float* __restrict__ Bm,
    const float* __restrict__ bias, float* __restrict__ C,
    int M, int N, int Kd,
    const int* __restrict__ rowidx, const float* __restrict__ roww,
    const int* __restrict__ Mcnt)
{
    int Meff = Mcnt ? *Mcnt : M;
    int m0 = blockIdx.y * 128;
    if (m0 >= Meff) return;
    int n0 = blockIdx.x * 128;

    __shared__ float As[16][136];   // [k][m], pitch 136 -> bank-conflict-free frags
    __shared__ float Bs[16][136];   // [k][n]

    int tid = threadIdx.x;
    int wid = tid >> 5, lane = tid & 31;
    int wm = (wid >> 2) * 64, wn = (wid & 3) * 32;
    int g = lane >> 2, tg = lane & 3;

    float4 acc[4][4];
#pragma unroll
    for (int i = 0; i < 4; i++)
#pragma unroll
        for (int j = 0; j < 4; j++) acc[i][j] = make_float4(0.f, 0.f, 0.f, 0.f);

    // global->smem A load mapping (2 rows per thread, 4 k each)
    int lr = tid >> 2;        // 0..63
    int lk = (tid & 3) * 4;   // k offset within 16
    int r0 = m0 + lr, r1 = m0 + lr + 64;
    bool v0 = r0 < Meff, v1 = r1 < Meff;
    int ga0 = 0, ga1 = 0;
    if (v0) ga0 = GATHER ? rowidx[r0] : r0;
    if (v1) ga1 = GATHER ? rowidx[r1] : r1;

    int bk = tid >> 5;        // 0..7
    int bn = (tid & 31) * 4;  // B tile col

    for (int k0 = 0; k0 < Kd; k0 += 16) {
        float4 a0 = make_float4(0.f,0.f,0.f,0.f), a1 = make_float4(0.f,0.f,0.f,0.f);
        if (v0) a0 = *(const float4*)(A + (size_t)ga0 * Kd + k0 + lk);
        if (v1) a1 = *(const float4*)(A + (size_t)ga1 * Kd + k0 + lk);
        float4 b0 = *(const float4*)(Bm + (size_t)(k0 + bk)     * N + n0 + bn);
        float4 b1 = *(const float4*)(Bm + (size_t)(k0 + bk + 8) * N + n0 + bn);
        __syncthreads();
        As[lk+0][lr] = a0.x; As[lk+1][lr] = a0.y; As[lk+2][lr] = a0.z; As[lk+3][lr] = a0.w;
        As[lk+0][lr+64] = a1.x; As[lk+1][lr+64] = a1.y; As[lk+2][lr+64] = a1.z; As[lk+3][lr+64] = a1.w;
        *(float4*)&Bs[bk][bn]     = b0;
        *(float4*)&Bs[bk + 8][bn] = b1;
        __syncthreads();

#pragma unroll
        for (int ks = 0; ks < 16; ks += 8) {
            uint32_t af[4][4], bf[4][2];
#pragma unroll
            for (int i = 0; i < 4; i++) {
                int mi = wm + i * 16;
                af[i][0] = f2tf(As[ks + tg][mi + g]);
                af[i][1] = f2tf(As[ks + tg][mi + 8 + g]);
                af[i][2] = f2tf(As[ks + 4 + tg][mi + g]);
                af[i][3] = f2tf(As[ks + 4 + tg][mi + 8 + g]);
            }
#pragma unroll
            for (int j = 0; j < 4; j++) {
                int nj = wn + j * 8;
                bf[j][0] = f2tf(Bs[ks + tg][nj + g]);
                bf[j][1] = f2tf(Bs[ks + 4 + tg][nj + g]);
            }
#pragma unroll
            for (int i = 0; i < 4; i++)
#pragma unroll
                for (int j = 0; j < 4; j++)
                    mma8(acc[i][j], af[i], bf[j]);
        }
    }

    // epilogue: each thread owns rows (m0+wm+i*16+g) and (+8), cols wn+j*8+tg*2 (+1)
#pragma unroll
    for (int i = 0; i < 4; i++) {
#pragma unroll
        for (int half = 0; half < 2; half++) {
            int m = m0 + wm + i * 16 + g + half * 8;
            if (m >= Meff) continue;
            int crow = m;
            float w = 1.f;
            if (MODE == 2) { crow = rowidx[m]; w = roww[m]; }
            float* cp = C + (size_t)crow * N;
#pragma unroll
            for (int j = 0; j < 4; j++) {
                int c = n0 + wn + j * 8 + tg * 2;
                float2 bp = *(const float2*)(bias + c);
                float v0 = (half ? acc[i][j].z : acc[i][j].x) + bp.x;
                float v1 = (half ? acc[i][j].w : acc[i][j].y) + bp.y;
                if (MODE == 1) { v0 = gelu_f(v0); v1 = gelu_f(v1); }
                if (MODE == 2) {
                    float2 old = *(float2*)(cp + c);
                    old.x += w * v0; old.y += w * v1;
                    *(float2*)(cp + c) = old;
                } else {
                    *(float2*)(cp + c) = make_float2(v0, v1);
                }
            }
        }
    }
}

// ---------------- flash attention, tf32 tensor cores ----------------
// Block: 128 threads (4 warps), q-tile 64 (16 rows/warp), kv-tile 64, HD=64.
// smem: Ks[64][68], Ps[64][68], Vs[64][72] (pitches chosen conflict-free)
#define KP 68
#define VP 72
__global__ void __launch_bounds__(128) attn_tc(
    const float* __restrict__ Q, const float* __restrict__ Kin,
    const float* __restrict__ Vin, float* __restrict__ Out)
{
    extern __shared__ float smx[];
    float* Ks = smx;                 // [64][KP]
    float* Ps = smx + 64 * KP;       // [64][KP]
    float* Vs = smx + 2 * 64 * KP;   // [64][VP]

    int bh = blockIdx.y;
    int b = bh >> 4, h = bh & 15;
    int q0 = blockIdx.x * 64;
    int tid = threadIdx.x;
    int wid = tid >> 5, lane = tid & 31;
    int g = lane >> 2, tg = lane & 3;
    int w16 = wid * 16;
    size_t base = (size_t)(b * Sc) * Dc + h * 64;
    const unsigned fullm = 0xffffffffu;

    // stage Q tile through Ks, build resident tf32 Q fragments
#pragma unroll
    for (int j = 0; j < 8; j++) {
        int idx = tid + j * 128;
        int r = idx >> 4, c = (idx & 15) * 4;
        *(float4*)&Ks[r * KP + c] = *(const float4*)(Q + base + (size_t)(q0 + r) * Dc + c);
    }
    __syncthreads();
    uint32_t qf[8][4];
#pragma unroll
    for (int d0 = 0; d0 < 8; d0++) {
        qf[d0][0] = f2tf(Ks[(w16 + g) * KP + d0 * 8 + tg]);
        qf[d0][1] = f2tf(Ks[(w16 + 8 + g) * KP + d0 * 8 + tg]);
        qf[d0][2] = f2tf(Ks[(w16 + g) * KP + d0 * 8 + 4 + tg]);
        qf[d0][3] = f2tf(Ks[(w16 + 8 + g) * KP + d0 * 8 + 4 + tg]);
    }

    float m0r = -1e30f, m1r = -1e30f;
    float l0r = 0.f, l1r = 0.f;
    float4 of[8];
#pragma unroll
    for (int j = 0; j < 8; j++) of[j] = make_float4(0.f, 0.f, 0.f, 0.f);

    for (int kv0 = 0; kv0 < Sc; kv0 += 64) {
        __syncthreads();
#pragma unroll
        for (int j = 0; j < 8; j++) {
            int idx = tid + j * 128;
            int r = idx >> 4, c = (idx & 15) * 4;
            *(float4*)&Ks[r * KP + c] = *(const float4*)(Kin + base + (size_t)(kv0 + r) * Dc + c);
            *(float4*)&Vs[r * VP + c] = *(const float4*)(Vin + base + (size_t)(kv0 + r) * Dc + c);
        }
        __syncthreads();

        // S = Q @ K^T  (warp: 16q x 64kv)
        float4 sa[8];
#pragma unroll
        for (int j = 0; j < 8; j++) sa[j] = make_float4(0.f, 0.f, 0.f, 0.f);
#pragma unroll
        for (int d0 = 0; d0 < 8; d0++) {
#pragma unroll
            for (int j = 0; j < 8; j++) {
                uint32_t bf[2];
                bf[0] = f2tf(Ks[(j * 8 + g) * KP + d0 * 8 + tg]);
                bf[1] = f2tf(Ks[(j * 8 + g) * KP + d0 * 8 + 4 + tg]);
                mma8(sa[j], qf[d0], bf);
            }
        }

        // online softmax (rows w16+g and w16+8+g; quad = lanes sharing g)
        float t0 = -1e30f, t1 = -1e30f;
#pragma unroll
        for (int j = 0; j < 8; j++) {
            sa[j].x *= 0.125f; sa[j].y *= 0.125f; sa[j].z *= 0.125f; sa[j].w *= 0.125f;
            t0 = fmaxf(t0, fmaxf(sa[j].x, sa[j].y));
            t1 = fmaxf(t1, fmaxf(sa[j].z, sa[j].w));
        }
        t0 = fmaxf(t0, __shfl_xor_sync(fullm, t0, 1));
        t0 = fmaxf(t0, __shfl_xor_sync(fullm, t0, 2));
        t1 = fmaxf(t1, __shfl_xor_sync(fullm, t1, 1));
        t1 = fmaxf(t1, __shfl_xor_sync(fullm, t1, 2));
        float mn0 = fmaxf(m0r, t0), mn1 = fmaxf(m1r, t1);
        float al0 = __expf(m0r - mn0), al1 = __expf(m1r - mn1);
        float rs0 = 0.f, rs1 = 0.f;
#pragma unroll
        for (int j = 0; j < 8; j++) {
            sa[j].x = __expf(sa[j].x - mn0); sa[j].y = __expf(sa[j].y - mn0);
            sa[j].z = __expf(sa[j].z - mn1); sa[j].w = __expf(sa[j].w - mn1);
            rs0 += sa[j].x + sa[j].y; rs1 += sa[j].z + sa[j].w;
        }
        rs0 += __shfl_xor_sync(fullm, rs0, 1); rs0 += __shfl_xor_sync(fullm, rs0, 2);
        rs1 += __shfl_xor_sync(fullm, rs1, 1); rs1 += __shfl_xor_sync(fullm, rs1, 2);
        l0r = l0r * al0 + rs0; l1r = l1r * al1 + rs1;
        m0r = mn0; m1r = mn1;
#pragma unroll
        for (int j = 0; j < 8; j++) {
            of[j].x *= al0; of[j].y *= al0; of[j].z *= al1; of[j].w *= al1;
        }

        // re-fragment P through warp-private smem
#pragma unroll
        for (int j = 0; j < 8; j++) {
            int col = j * 8 + tg * 2;
            Ps[(w16 + g) * KP + col]     = sa[j].x;
            Ps[(w16 + g) * KP + col + 1] = sa[j].y;
            Ps[(w16 + 8 + g) * KP + col]     = sa[j].z;
            Ps[(w16 + 8 + g) * KP + col + 1] = sa[j].w;
        }
        __syncwarp();

        // O += P @ V  (k-dim = kv 64, n-dim = d 64)
#pragma unroll
        for (int k0 = 0; k0 < 8; k0++) {
            uint32_t af[4];
            af[0] = f2tf(Ps[(w16 + g) * KP + k0 * 8 + tg]);
            af[1] = f2tf(Ps[(w16 + 8 + g) * KP + k0 * 8 + tg]);
            af[2] = f2tf(Ps[(w16 + g) * KP + k0 * 8 + 4 + tg]);
            af[3] = f2tf(Ps[(w16 + 8 + g) * KP + k0 * 8 + 4 + tg]);
#pragma unroll
            for (int j = 0; j < 8; j++) {
                uint32_t bf[2];
                bf[0] = f2tf(Vs[(k0 * 8 + tg) * VP + j * 8 + g]);
                bf[1] = f2tf(Vs[(k0 * 8 + 4 + tg) * VP + j * 8 + g]);
                mma8(of[j], af, bf);
            }
        }
    }

    float inv0 = 1.f / l0r, inv1 = 1.f / l1r;
#pragma unroll
    for (int j = 0; j < 8; j++) {
        int col = j * 8 + tg * 2;
        float* p0 = Out + base + (size_t)(q0 + w16 + g) * Dc + col;
        float* p1 = Out + base + (size_t)(q0 + w16 + 8 + g) * Dc + col;
        *(float2*)p0 = make_float2(of[j].x * inv0, of[j].y * inv0);
        *(float2*)p1 = make_float2(of[j].z * inv1, of[j].w * inv1);
    }
}

// ---------------- residual + layernorm ----------------
__global__ void __launch_bounds__(256) add_ln_kernel(
    const float* __restrict__ xin, const float* __restrict__ res,
    const float* __restrict__ g, const float* __restrict__ bta,
    float* __restrict__ out)
{
    int t = blockIdx.x;
    int tid = threadIdx.x;
    const float4 xv = ((const float4*)(xin + (size_t)t * Dc))[tid];
    const float4 rv = ((const float4*)(res + (size_t)t * Dc))[tid];
    float v[4] = {xv.x + rv.x, xv.y + rv.y, xv.z + rv.z, xv.w + rv.w};
    float s  = v[0] + v[1] + v[2] + v[3];
    float sq = v[0]*v[0] + v[1]*v[1] + v[2]*v[2] + v[3]*v[3];
#pragma unroll
    for (int off = 16; off; off >>= 1) {
        s  += __shfl_xor_sync(0xffffffffu, s, off);
        sq += __shfl_xor_sync(0xffffffffu, sq, off);
    }
    __shared__ float ss[8], qq[8];
    __shared__ float smu, srstd;
    int wid = tid >> 5;
    if ((tid & 31) == 0) { ss[wid] = s; qq[wid] = sq; }
    __syncthreads();
    if (tid == 0) {
        float ts = 0.f, tq = 0.f;
#pragma unroll
        for (int i = 0; i < 8; i++) { ts += ss[i]; tq += qq[i]; }
        float mu = ts / (float)Dc;
        float var = tq / (float)Dc - mu * mu;
        smu = mu; srstd = rsqrtf(var + 1e-5f);
    }
    __syncthreads();
    float mu = smu, rstd = srstd;
    float4 g4 = ((const float4*)g)[tid];
    float4 b4 = ((const float4*)bta)[tid];
    float4 o4;
    o4.x = (v[0]-mu)*rstd*g4.x + b4.x;
    o4.y = (v[1]-mu)*rstd*g4.y + b4.y;
    o4.z = (v[2]-mu)*rstd*g4.z + b4.z;
    o4.w = (v[3]-mu)*rstd*g4.w + b4.w;
    ((float4*)(out + (size_t)t * Dc))[tid] = o4;
}

// ---------------- gate: logits, softmax, top-2, routing lists ----------------
__global__ void __launch_bounds__(256) gate_kernel(
    const float* __restrict__ x1, const float* __restrict__ gW,
    const float* __restrict__ gb)
{
    int t = blockIdx.x;
    int tid = threadIdx.x;
    float part[Ec];
#pragma unroll
    for (int e = 0; e < Ec; e++) part[e] = 0.f;
    const float* xr = x1 + (size_t)t * Dc;
    for (int d = tid; d < Dc; d += 256) {
        float xv = xr[d];
        const float* wr = gW + d * Ec;
#pragma unroll
        for (int e = 0; e < Ec; e++) part[e] += xv * wr[e];
    }
    __shared__ float sm[Ec][264];
#pragma unroll
    for (int e = 0; e < Ec; e++) sm[e][tid] = part[e];
    __syncthreads();
    for (int off = 128; off; off >>= 1) {
        if (tid < off) {
#pragma unroll
            for (int e = 0; e < Ec; e++) sm[e][tid] += sm[e][tid + off];
        }
        __syncthreads();
    }
    if (tid == 0) {
        float lg[Ec], sc[Ec];
        float m = -1e30f;
#pragma unroll
        for (int e = 0; e < Ec; e++) { lg[e] = sm[e][0] + gb[e]; m = fmaxf(m, lg[e]); }
        float sum = 0.f;
#pragma unroll
        for (int e = 0; e < Ec; e++) { sc[e] = expf(lg[e] - m); sum += sc[e]; }
        float inv = 1.f / sum;
#pragma unroll
        for (int e = 0; e < Ec; e++) { sc[e] *= inv; g_scores[t * Ec + e] = sc[e]; }
        int a1 = 0;
#pragma unroll
        for (int e = 1; e < Ec; e++) if (sc[e] > sc[a1]) a1 = e;
        int a2 = (a1 == 0) ? 1 : 0;
#pragma unroll
        for (int e = 0; e < Ec; e++) if (e != a1 && sc[e] > sc[a2]) a2 = e;
        float ws = sc[a1] + sc[a2];
        float w1 = sc[a1] / ws, w2 = sc[a2] / ws;
        int p1 = atomicAdd(&g_cnt[a1], 1);
        g_eidx[a1 * Tc + p1] = t; g_ewgt[a1 * Tc + p1] = w1;
        int p2 = atomicAdd(&g_cnt[a2], 1);
        g_eidx[a2 * Tc + p2] = t; g_ewgt[a2 * Tc + p2] = w2;
    }
}

// ---------------- aux loss (deterministic fixed-order reduction) ----------------
__global__ void __launch_bounds__(256) aux_kernel(float* __restrict__ out)
{
    int tid = threadIdx.x;
    float part[Ec];
#pragma unroll
    for (int e = 0; e < Ec; e++) part[e] = 0.f;
    for (int t = tid; t < Tc; t += 256) {
#pragma unroll
        for (int e = 0; e < Ec; e++) part[e] += g_scores[t * Ec + e];
    }
    __shared__ float sm[Ec][264];
#pragma unroll
    for (int e = 0; e < Ec; e++) sm[e][tid] = part[e];
    __syncthreads();
    for (int off = 128; off; off >>= 1) {
        if (tid < off) {
#pragma unroll
            for (int e = 0; e < Ec; e++) sm[e][tid] += sm[e][tid + off];
        }
        __syncthreads();
    }
    if (tid == 0) {
        float aux = 0.f;
#pragma unroll
        for (int e = 0; e < Ec; e++) {
            float ef = (float)g_cnt[e] / (float)(Tc * Kc);
            float rw = sm[e][0] / (float)Tc;
            aux += ef * rw;
        }
        out[0] = aux * (float)Ec;
    }
}

// ---------------- state reset (graph replays need clean state) ----------------
__global__ void zero_cnt_kernel() {
    if (threadIdx.x < Ec) g_cnt[threadIdx.x] = 0;
}
__global__ void zero_moe_kernel() {
    size_t i = ((size_t)blockIdx.x * 256 + threadIdx.x) * 4;
    *(float4*)(g_moe + i) = make_float4(0.f, 0.f, 0.f, 0.f);
}

// ---------------- launch ----------------
extern "C" void kernel_launch(void* const* d_in, const int* in_sizes, int n_in,
                              void* d_out, int out_size)
{
    (void)in_sizes; (void)n_in; (void)out_size;
    const float* x     = (const float*)d_in[0];
    const float* Wq    = (const float*)d_in[1];
    const float* bq    = (const float*)d_in[2];
    const float* Wk    = (const float*)d_in[3];
    const float* bk    = (const float*)d_in[4];
    const float* Wv    = (const float*)d_in[5];
    const float* bv    = (const float*)d_in[6];
    const float* Wo    = (const float*)d_in[7];
    const float* bo    = (const float*)d_in[8];
    const float* g1    = (const float*)d_in[9];
    const float* beta1 = (const float*)d_in[10];
    const float* gateW = (const float*)d_in[11];
    const float* gateb = (const float*)d_in[12];
    const float* eW1   = (const float*)d_in[13];
    const float* eb1   = (const float*)d_in[14];
    const float* eW2   = (const float*)d_in[15];
    const float* eb2   = (const float*)d_in[16];
    const float* g2    = (const float*)d_in[17];
    const float* beta2 = (const float*)d_in[18];
    float* out = (float*)d_out;

    float *pQ, *pK, *pV, *pAO, *pP, *pX1, *pMoe, *pH, *pWgt;
    int *pCnt, *pIdx;
    cudaGetSymbolAddress((void**)&pQ,   g_Q);
    cudaGetSymbolAddress((void**)&pK,   g_Kb);
    cudaGetSymbolAddress((void**)&pV,   g_Vb);
    cudaGetSymbolAddress((void**)&pAO,  g_AO);
    cudaGetSymbolAddress((void**)&pP,   g_P);
    cudaGetSymbolAddress((void**)&pX1,  g_X1);
    cudaGetSymbolAddress((void**)&pMoe, g_moe);
    cudaGetSymbolAddress((void**)&pH,   g_H);
    cudaGetSymbolAddress((void**)&pCnt, g_cnt);
    cudaGetSymbolAddress((void**)&pIdx, g_eidx);
    cudaGetSymbolAddress((void**)&pWgt, g_ewgt);

    const int attn_smem = (2 * 64 * KP + 64 * VP) * (int)sizeof(float);  // 53248
    cudaFuncSetAttribute(attn_tc, cudaFuncAttributeMaxDynamicSharedMemorySize, attn_smem);

    zero_cnt_kernel<<<1, 32>>>();
    zero_moe_kernel<<<(Tc * Dc) / 1024, 256>>>();

    dim3 gD(Dc / 128, Tc / 128);   // (8, 64)
    gemm_tc<0,false><<<gD, 256>>>(x, Wq, bq, pQ, Tc, Dc, Dc, nullptr, nullptr, nullptr);
    gemm_tc<0,false><<<gD, 256>>>(x, Wk, bk, pK, Tc, Dc, Dc, nullptr, nullptr, nullptr);
    gemm_tc<0,false><<<gD, 256>>>(x, Wv, bv, pV, Tc, Dc, Dc, nullptr, nullptr, nullptr);

    attn_tc<<<dim3(Sc / 64, Bc * Hc), 128, attn_smem>>>(pQ, pK, pV, pAO);

    gemm_tc<0,false><<<gD, 256>>>(pAO, Wo, bo, pP, Tc, Dc, Dc, nullptr, nullptr, nullptr);
    add_ln_kernel<<<Tc, 256>>>(x, pP, g1, beta1, pX1);

    gate_kernel<<<Tc, 256>>>(pX1, gateW, gateb);

    dim3 gF(Fc / 128, Tc / 128);   // (32, 64)
    for (int e = 0; e < Ec; e++) {
        gemm_tc<1,true><<<gF, 256>>>(pX1, eW1 + (size_t)e * Dc * Fc, eb1 + e * Fc,
                                     pH, Tc, Fc, Dc,
                                     pIdx + e * Tc, nullptr, pCnt + e);
        gemm_tc<2,false><<<gD, 256>>>(pH, eW2 + (size_t)e * Fc * Dc, eb2 + e * Dc,
                                      pMoe, Tc, Dc, Fc,
                                      pIdx + e * Tc, pWgt + e * Tc, pCnt + e);
    }

    add_ln_kernel<<<Tc, 256>>>(pX1, pMoe, g2, beta2, out);
    aux_kernel<<<1, 256>>>(out + (size_t)Tc * Dc);
}

// round 7
// speedup vs baseline: 3.8118x; 1.0619x over previous
#include <cuda_runtime.h>
#include <cstdint>

#define Bc 4
#define Sc 2048
#define Dc 1024
#define Hc 16
#define HDc 64
#define Fc 4096
#define Ec 8
#define Kc 2
#define Tc (Bc*Sc)   /* 8192 */

// ---------------- scratch (static device globals; no allocation) ----------------
__device__ float g_Q[Tc*Dc];
__device__ float g_Kb[Tc*Dc];
__device__ float g_Vb[Tc*Dc];
__device__ float g_AO[Tc*Dc];
__device__ float g_P[Tc*Dc];
__device__ float g_X1[Tc*Dc];
__device__ float g_moe[Tc*Dc];
__device__ float g_H[(size_t)Tc*Fc];
__device__ int   g_cnt[Ec];
__device__ int   g_eidx[Ec*Tc];
__device__ float g_ewgt[Ec*Tc];
__device__ float g_scores[Tc*Ec];

__device__ __forceinline__ float gelu_f(float v) {
    return 0.5f * v * (1.0f + erff(v * 0.70710678118654752f));
}

// tf32 convert (round-to-nearest)
__device__ __forceinline__ uint32_t f2tf(float f) {
    uint32_t u; asm("cvt.rna.tf32.f32 %0, %1;" : "=r"(u) : "f"(f)); return u;
}

// D += A(16x8,row) * B(8x8,col) ; fp32 accumulate
__device__ __forceinline__ void mma8(float4& d, const uint32_t* a, const uint32_t* b) {
    asm volatile(
        "mma.sync.aligned.m16n8k8.row.col.f32.tf32.tf32.f32 "
        "{%0,%1,%2,%3}, {%4,%5,%6,%7}, {%8,%9}, {%0,%1,%2,%3};\n"
        : "+f"(d.x), "+f"(d.y), "+f"(d.z), "+f"(d.w)
        : "r"(a[0]), "r"(a[1]), "r"(a[2]), "r"(a[3]), "r"(b[0]), "r"(b[1]));
}

// ---------------- tf32 tensor-core GEMM, double-buffered, fragment-major A ----------------
// Tile 128x128, Ktile 16, 8 warps (2x4), warp tile 64x32, thread 16x8 over 4x4 mmas.
// A smem: fragment-major [buf][ks][mtile][slot16][reg], slot16 = g*4 + (tg^(g>>1)),
//   values pre-converted to tf32 -> reader does 4 conflict-free LDS.128 per ks.
// B smem: [buf][k][n] pitch 136, pre-converted tf32 -> conflict-free scalar reads.
// MODE 0: store (bias add); MODE 1: store gelu; MODE 2: C[rowidx]+=w*(..); GATHER via rowidx
__device__ __forceinline__ void storeA_frag(uint32_t* dstks, int mloc, int khalf, float4 v) {
    int mtile = mloc >> 4, g = mloc & 7, half = (mloc >> 3) & 1;
    int reg = khalf * 2 + half;
    uint32_t* base = dstks + mtile * 128;
    int sw = g >> 1;
    base[(g * 4 + (0 ^ sw)) * 4 + reg] = f2tf(v.x);
    base[(g * 4 + (1 ^ sw)) * 4 + reg] = f2tf(v.y);
    base[(g * 4 + (2 ^ sw)) * 4 + reg] = f2tf(v.z);
    base[(g * 4 + (3 ^ sw)) * 4 + reg] = f2tf(v.w);
}

template<int MODE, bool GATHER>
__global__ void __launch_bounds__(256, 1) gemm_tc(
    const float* __restrict__ A, const float* __restrict__ Bm,
    const float* __restrict__ bias, float* __restrict__ C,
    int M, int N, int Kd,
    const int* __restrict__ rowidx, const float* __restrict__ roww,
    const int* __restrict__ Mcnt)
{
    int Meff = Mcnt ? *Mcnt : M;
    int m0 = blockIdx.y * 128;
    if (m0 >= Meff) return;
    int n0 = blockIdx.x * 128;

    __shared__ uint32_t Af[2][2][8][32][4];   // 16KB
    __shared__ uint32_t Bf[2][16][136];       // 17KB

    int tid = threadIdx.x;
    int wid = tid >> 5, lane = tid & 31;
    int wrow = wid >> 2, wn = (wid & 3) * 32;
    int g = lane >> 2, tg = lane & 3;
    int aidx = g * 4 + (tg ^ (g >> 1));

    float4 acc[4][4];
#pragma unroll
    for (int i = 0; i < 4; i++)
#pragma unroll
        for (int j = 0; j < 4; j++) acc[i][j] = make_float4(0.f, 0.f, 0.f, 0.f);

    // A loader: 2 rows x 4 k-values per thread
    int lr = tid >> 2;
    int lk = (tid & 3) * 4;
    int ks_w = lk >> 3;
    int khalf = (lk >> 2) & 1;
    int r0g = m0 + lr, r1g = m0 + lr + 64;
    bool v0 = r0g < Meff, v1 = r1g < Meff;
    int ga0 = 0, ga1 = 0;
    if (v0) ga0 = GATHER ? rowidx[r0g] : r0g;
    if (v1) ga1 = GATHER ? rowidx[r1g] : r1g;
    // B loader: rows bk, bk+8; 4 n-values
    int bk = tid >> 5;
    int bn = (tid & 31) * 4;

    int nk = Kd >> 4;
    float4 a0s, a1s, b0s, b1s;

    // prologue: tile 0 -> buf 0
    a0s = v0 ? *(const float4*)(A + (size_t)ga0 * Kd + lk) : make_float4(0.f,0.f,0.f,0.f);
    a1s = v1 ? *(const float4*)(A + (size_t)ga1 * Kd + lk) : make_float4(0.f,0.f,0.f,0.f);
    b0s = *(const float4*)(Bm + (size_t)bk * N + n0 + bn);
    b1s = *(const float4*)(Bm + (size_t)(bk + 8) * N + n0 + bn);
    storeA_frag(&Af[0][ks_w][0][0][0], lr, khalf, a0s);
    storeA_frag(&Af[0][ks_w][0][0][0], lr + 64, khalf, a1s);
    {
        uint4 t0 = make_uint4(f2tf(b0s.x), f2tf(b0s.y), f2tf(b0s.z), f2tf(b0s.w));
        uint4 t1 = make_uint4(f2tf(b1s.x), f2tf(b1s.y), f2tf(b1s.z), f2tf(b1s.w));
        *(uint4*)&Bf[0][bk][bn]     = t0;
        *(uint4*)&Bf[0][bk + 8][bn] = t1;
    }
    __syncthreads();

    for (int i = 0; i < nk; i++) {
        int buf = i & 1;
        if (i + 1 < nk) {
            int k0 = (i + 1) << 4;
            a0s = v0 ? *(const float4*)(A + (size_t)ga0 * Kd + k0 + lk) : make_float4(0.f,0.f,0.f,0.f);
            a1s = v1 ? *(const float4*)(A + (size_t)ga1 * Kd + k0 + lk) : make_float4(0.f,0.f,0.f,0.f);
            b0s = *(const float4*)(Bm + (size_t)(k0 + bk) * N + n0 + bn);
            b1s = *(const float4*)(Bm + (size_t)(k0 + bk + 8) * N + n0 + bn);
        }

#pragma unroll
        for (int ks = 0; ks < 2; ks++) {
            uint4 af4[4];
            const uint4* Ab = (const uint4*)&Af[buf][ks][0][0][0];
#pragma unroll
            for (int i2 = 0; i2 < 4; i2++)
                af4[i2] = Ab[(wrow * 4 + i2) * 32 + aidx];
            uint32_t bfr[4][2];
#pragma unroll
            for (int j = 0; j < 4; j++) {
                bfr[j][0] = Bf[buf][ks * 8 + tg][wn + j * 8 + g];
                bfr[j][1] = Bf[buf][ks * 8 + 4 + tg][wn + j * 8 + g];
            }
#pragma unroll
            for (int i2 = 0; i2 < 4; i2++)
#pragma unroll
                for (int j = 0; j < 4; j++)
                    mma8(acc[i2][j], (const uint32_t*)&af4[i2], bfr[j]);
        }

        if (i + 1 < nk) {
            int nb = buf ^ 1;
            storeA_frag(&Af[nb][ks_w][0][0][0], lr, khalf, a0s);
            storeA_frag(&Af[nb][ks_w][0][0][0], lr + 64, khalf, a1s);
            uint4 t0 = make_uint4(f2tf(b0s.x), f2tf(b0s.y), f2tf(b0s.z), f2tf(b0s.w));
            uint4 t1 = make_uint4(f2tf(b1s.x), f2tf(b1s.y), f2tf(b1s.z), f2tf(b1s.w));
            *(uint4*)&Bf[nb][bk][bn]     = t0;
            *(uint4*)&Bf[nb][bk + 8][bn] = t1;
        }
        __syncthreads();
    }

    // epilogue: thread owns rows m0+wrow*64+i*16+g(+8), cols n0+wn+j*8+tg*2(+1)
#pragma unroll
    for (int i = 0; i < 4; i++) {
#pragma unroll
        for (int half = 0; half < 2; half++) {
            int m = m0 + wrow * 64 + i * 16 + g + half * 8;
            if (m >= Meff) continue;
            int crow = m;
            float w = 1.f;
            if (MODE == 2) { crow = rowidx[m]; w = roww[m]; }
            float* cp = C + (size_t)crow * N;
#pragma unroll
            for (int j = 0; j < 4; j++) {
                int c = n0 + wn + j * 8 + tg * 2;
                float2 bp = *(const float2*)(bias + c);
                float u0 = (half ? acc[i][j].z : acc[i][j].x) + bp.x;
                float u1 = (half ? acc[i][j].w : acc[i][j].y) + bp.y;
                if (MODE == 1) { u0 = gelu_f(u0); u1 = gelu_f(u1); }
                if (MODE == 2) {
                    float2 old = *(float2*)(cp + c);
                    old.x += w * u0; old.y += w * u1;
                    *(float2*)(cp + c) = old;
                } else {
                    *(float2*)(cp + c) = make_float2(u0, u1);
                }
            }
        }
    }
}

// ---------------- flash attention, tf32 tensor cores, pre-converted smem ----------------
// Block: 128 threads (4 warps), q-tile 64 (16 rows/warp), kv-tile 64, HD=64.
// Ks/Ps/Vs hold tf32 bit patterns (uint32) -> zero CVT in inner loops.
#define KP 68
#define VP 72
__global__ void __launch_bounds__(128) attn_tc(
    const float* __restrict__ Q, const float* __restrict__ Kin,
    const float* __restrict__ Vin, float* __restrict__ Out)
{
    extern __shared__ uint32_t smx[];
    uint32_t* Ks = smx;                 // [64][KP]
    uint32_t* Ps = smx + 64 * KP;       // [64][KP]
    uint32_t* Vs = smx + 2 * 64 * KP;   // [64][VP]

    int bh = blockIdx.y;
    int b = bh >> 4, h = bh & 15;
    int q0 = blockIdx.x * 64;
    int tid = threadIdx.x;
    int wid = tid >> 5, lane = tid & 31;
    int g = lane >> 2, tg = lane & 3;
    int w16 = wid * 16;
    size_t base = (size_t)(b * Sc) * Dc + h * 64;
    const unsigned fullm = 0xffffffffu;

    // stage Q tile (tf32) through Ks, build resident Q fragments
#pragma unroll
    for (int j = 0; j < 8; j++) {
        int idx = tid + j * 128;
        int r = idx >> 4, c = (idx & 15) * 4;
        float4 q4 = *(const float4*)(Q + base + (size_t)(q0 + r) * Dc + c);
        *(uint4*)&Ks[r * KP + c] = make_uint4(f2tf(q4.x), f2tf(q4.y), f2tf(q4.z), f2tf(q4.w));
    }
    __syncthreads();
    uint32_t qf[8][4];
#pragma unroll
    for (int d0 = 0; d0 < 8; d0++) {
        qf[d0][0] = Ks[(w16 + g) * KP + d0 * 8 + tg];
        qf[d0][1] = Ks[(w16 + 8 + g) * KP + d0 * 8 + tg];
        qf[d0][2] = Ks[(w16 + g) * KP + d0 * 8 + 4 + tg];
        qf[d0][3] = Ks[(w16 + 8 + g) * KP + d0 * 8 + 4 + tg];
    }

    float m0r = -1e30f, m1r = -1e30f;
    float l0r = 0.f, l1r = 0.f;
    float4 of[8];
#pragma unroll
    for (int j = 0; j < 8; j++) of[j] = make_float4(0.f, 0.f, 0.f, 0.f);

    for (int kv0 = 0; kv0 < Sc; kv0 += 64) {
        __syncthreads();
#pragma unroll
        for (int j = 0; j < 8; j++) {
            int idx = tid + j * 128;
            int r = idx >> 4, c = (idx & 15) * 4;
            float4 k4 = *(const float4*)(Kin + base + (size_t)(kv0 + r) * Dc + c);
            float4 v4 = *(const float4*)(Vin + base + (size_t)(kv0 + r) * Dc + c);
            *(uint4*)&Ks[r * KP + c] = make_uint4(f2tf(k4.x), f2tf(k4.y), f2tf(k4.z), f2tf(k4.w));
            *(uint4*)&Vs[r * VP + c] = make_uint4(f2tf(v4.x), f2tf(v4.y), f2tf(v4.z), f2tf(v4.w));
        }
        __syncthreads();

        // S = Q @ K^T
        float4 sa[8];
#pragma unroll
        for (int j = 0; j < 8; j++) sa[j] = make_float4(0.f, 0.f, 0.f, 0.f);
#pragma unroll
        for (int d0 = 0; d0 < 8; d0++) {
#pragma unroll
            for (int j = 0; j < 8; j++) {
                uint32_t bf[2];
                bf[0] = Ks[(j * 8 + g) * KP + d0 * 8 + tg];
                bf[1] = Ks[(j * 8 + g) * KP + d0 * 8 + 4 + tg];
                mma8(sa[j], qf[d0], bf);
            }
        }

        // online softmax (rows w16+g and w16+8+g)
        float t0 = -1e30f, t1 = -1e30f;
#pragma unroll
        for (int j = 0; j < 8; j++) {
            sa[j].x *= 0.125f; sa[j].y *= 0.125f; sa[j].z *= 0.125f; sa[j].w *= 0.125f;
            t0 = fmaxf(t0, fmaxf(sa[j].x, sa[j].y));
            t1 = fmaxf(t1, fmaxf(sa[j].z, sa[j].w));
        }
        t0 = fmaxf(t0, __shfl_xor_sync(fullm, t0, 1));
        t0 = fmaxf(t0, __shfl_xor_sync(fullm, t0, 2));
        t1 = fmaxf(t1, __shfl_xor_sync(fullm, t1, 1));
        t1 = fmaxf(t1, __shfl_xor_sync(fullm, t1, 2));
        float mn0 = fmaxf(m0r, t0), mn1 = fmaxf(m1r, t1);
        float al0 = __expf(m0r - mn0), al1 = __expf(m1r - mn1);
        float rs0 = 0.f, rs1 = 0.f;
#pragma unroll
        for (int j = 0; j < 8; j++) {
            sa[j].x = __expf(sa[j].x - mn0); sa[j].y = __expf(sa[j].y - mn0);
            sa[j].z = __expf(sa[j].z - mn1); sa[j].w = __expf(sa[j].w - mn1);
            rs0 += sa[j].x + sa[j].y; rs1 += sa[j].z + sa[j].w;
        }
        rs0 += __shfl_xor_sync(fullm, rs0, 1); rs0 += __shfl_xor_sync(fullm, rs0, 2);
        rs1 += __shfl_xor_sync(fullm, rs1, 1); rs1 += __shfl_xor_sync(fullm, rs1, 2);
        l0r = l0r * al0 + rs0; l1r = l1r * al1 + rs1;
        m0r = mn0; m1r = mn1;
#pragma unroll
        for (int j = 0; j < 8; j++) {
            of[j].x *= al0; of[j].y *= al0; of[j].z *= al1; of[j].w *= al1;
        }

        // re-fragment P (tf32) through warp-private smem
#pragma unroll
        for (int j = 0; j < 8; j++) {
            int col = j * 8 + tg * 2;
            Ps[(w16 + g) * KP + col]     = f2tf(sa[j].x);
            Ps[(w16 + g) * KP + col + 1] = f2tf(sa[j].y);
            Ps[(w16 + 8 + g) * KP + col]     = f2tf(sa[j].z);
            Ps[(w16 + 8 + g) * KP + col + 1] = f2tf(sa[j].w);
        }
        __syncwarp();

        // O += P @ V
#pragma unroll
        for (int k0 = 0; k0 < 8; k0++) {
            uint32_t af[4];
            af[0] = Ps[(w16 + g) * KP + k0 * 8 + tg];
            af[1] = Ps[(w16 + 8 + g) * KP + k0 * 8 + tg];
            af[2] = Ps[(w16 + g) * KP + k0 * 8 + 4 + tg];
            af[3] = Ps[(w16 + 8 + g) * KP + k0 * 8 + 4 + tg];
#pragma unroll
            for (int j = 0; j < 8; j++) {
                uint32_t bf[2];
                bf[0] = Vs[(k0 * 8 + tg) * VP + j * 8 + g];
                bf[1] = Vs[(k0 * 8 + 4 + tg) * VP + j * 8 + g];
                mma8(of[j], af, bf);
            }
        }
    }

    float inv0 = 1.f / l0r, inv1 = 1.f / l1r;
#pragma unroll
    for (int j = 0; j < 8; j++) {
        int col = j * 8 + tg * 2;
        float* p0 = Out + base + (size_t)(q0 + w16 + g) * Dc + col;
        float* p1 = Out + base + (size_t)(q0 + w16 + 8 + g) * Dc + col;
        *(float2*)p0 = make_float2(of[j].x * inv0, of[j].y * inv0);
        *(float2*)p1 = make_float2(of[j].z * inv1, of[j].w * inv1);
    }
}

// ---------------- residual + layernorm ----------------
__global__ void __launch_bounds__(256) add_ln_kernel(
    const float* __restrict__ xin, const float* __restrict__ res,
    const float* __restrict__ g, const float* __restrict__ bta,
    float* __restrict__ out)
{
    int t = blockIdx.x;
    int tid = threadIdx.x;
    const float4 xv = ((const float4*)(xin + (size_t)t * Dc))[tid];
    const float4 rv = ((const float4*)(res + (size_t)t * Dc))[tid];
    float v[4] = {xv.x + rv.x, xv.y + rv.y, xv.z + rv.z, xv.w + rv.w};
    float s  = v[0] + v[1] + v[2] + v[3];
    float sq = v[0]*v[0] + v[1]*v[1] + v[2]*v[2] + v[3]*v[3];
#pragma unroll
    for (int off = 16; off; off >>= 1) {
        s  += __shfl_xor_sync(0xffffffffu, s, off);
        sq += __shfl_xor_sync(0xffffffffu, sq, off);
    }
    __shared__ float ss[8], qq[8];
    __shared__ float smu, srstd;
    int wid = tid >> 5;
    if ((tid & 31) == 0) { ss[wid] = s; qq[wid] = sq; }
    __syncthreads();
    if (tid == 0) {
        float ts = 0.f, tq = 0.f;
#pragma unroll
        for (int i = 0; i < 8; i++) { ts += ss[i]; tq += qq[i]; }
        float mu = ts / (float)Dc;
        float var = tq / (float)Dc - mu * mu;
        smu = mu; srstd = rsqrtf(var + 1e-5f);
    }
    __syncthreads();
    float mu = smu, rstd = srstd;
    float4 g4 = ((const float4*)g)[tid];
    float4 b4 = ((const float4*)bta)[tid];
    float4 o4;
    o4.x = (v[0]-mu)*rstd*g4.x + b4.x;
    o4.y = (v[1]-mu)*rstd*g4.y + b4.y;
    o4.z = (v[2]-mu)*rstd*g4.z + b4.z;
    o4.w = (v[3]-mu)*rstd*g4.w + b4.w;
    ((float4*)(out + (size_t)t * Dc))[tid] = o4;
}

// ---------------- gate: logits, softmax, top-2, routing lists ----------------
__global__ void __launch_bounds__(256) gate_kernel(
    const float* __restrict__ x1, const float* __restrict__ gW,
    const float* __restrict__ gb)
{
    int t = blockIdx.x;
    int tid = threadIdx.x;
    float part[Ec];
#pragma unroll
    for (int e = 0; e < Ec; e++) part[e] = 0.f;
    const float* xr = x1 + (size_t)t * Dc;
    for (int d = tid; d < Dc; d += 256) {
        float xv = xr[d];
        const float* wr = gW + d * Ec;
#pragma unroll
        for (int e = 0; e < Ec; e++) part[e] += xv * wr[e];
    }
    __shared__ float sm[Ec][264];
#pragma unroll
    for (int e = 0; e < Ec; e++) sm[e][tid] = part[e];
    __syncthreads();
    for (int off = 128; off; off >>= 1) {
        if (tid < off) {
#pragma unroll
            for (int e = 0; e < Ec; e++) sm[e][tid] += sm[e][tid + off];
        }
        __syncthreads();
    }
    if (tid == 0) {
        float lg[Ec], sc[Ec];
        float m = -1e30f;
#pragma unroll
        for (int e = 0; e < Ec; e++) { lg[e] = sm[e][0] + gb[e]; m = fmaxf(m, lg[e]); }
        float sum = 0.f;
#pragma unroll
        for (int e = 0; e < Ec; e++) { sc[e] = expf(lg[e] - m); sum += sc[e]; }
        float inv = 1.f / sum;
#pragma unroll
        for (int e = 0; e < Ec; e++) { sc[e] *= inv; g_scores[t * Ec + e] = sc[e]; }
        int a1 = 0;
#pragma unroll
        for (int e = 1; e < Ec; e++) if (sc[e] > sc[a1]) a1 = e;
        int a2 = (a1 == 0) ? 1 : 0;
#pragma unroll
        for (int e = 0; e < Ec; e++) if (e != a1 && sc[e] > sc[a2]) a2 = e;
        float ws = sc[a1] + sc[a2];
        float w1 = sc[a1] / ws, w2 = sc[a2] / ws;
        int p1 = atomicAdd(&g_cnt[a1], 1);
        g_eidx[a1 * Tc + p1] = t; g_ewgt[a1 * Tc + p1] = w1;
        int p2 = atomicAdd(&g_cnt[a2], 1);
        g_eidx[a2 * Tc + p2] = t; g_ewgt[a2 * Tc + p2] = w2;
    }
}

// ---------------- aux loss (deterministic fixed-order reduction) ----------------
__global__ void __launch_bounds__(256) aux_kernel(float* __restrict__ out)
{
    int tid = threadIdx.x;
    float part[Ec];
#pragma unroll
    for (int e = 0; e < Ec; e++) part[e] = 0.f;
    for (int t = tid; t < Tc; t += 256) {
#pragma unroll
        for (int e = 0; e < Ec; e++) part[e] += g_scores[t * Ec + e];
    }
    __shared__ float sm[Ec][264];
#pragma unroll
    for (int e = 0; e < Ec; e++) sm[e][tid] = part[e];
    __syncthreads();
    for (int off = 128; off; off >>= 1) {
        if (tid < off) {
#pragma unroll
            for (int e = 0; e < Ec; e++) sm[e][tid] += sm[e][tid + off];
        }
        __syncthreads();
    }
    if (tid == 0) {
        float aux = 0.f;
#pragma unroll
        for (int e = 0; e < Ec; e++) {
            float ef = (float)g_cnt[e] / (float)(Tc * Kc);
            float rw = sm[e][0] / (float)Tc;
            aux += ef * rw;
        }
        out[0] = aux * (float)Ec;
    }
}

// ---------------- state reset (graph replays need clean state) ----------------
__global__ void zero_cnt_kernel() {
    if (threadIdx.x < Ec) g_cnt[threadIdx.x] = 0;
}
__global__ void zero_moe_kernel() {
    size_t i = ((size_t)blockIdx.x * 256 + threadIdx.x) * 4;
    *(float4*)(g_moe + i) = make_float4(0.f, 0.f, 0.f, 0.f);
}

// ---------------- launch ----------------
extern "C" void kernel_launch(void* const* d_in, const int* in_sizes, int n_in,
                              void* d_out, int out_size)
{
    (void)in_sizes; (void)n_in; (void)out_size;
    const float* x     = (const float*)d_in[0];
    const float* Wq    = (const float*)d_in[1];
    const float* bq    = (const float*)d_in[2];
    const float* Wk    = (const float*)d_in[3];
    const float* bk    = (const float*)d_in[4];
    const float* Wv    = (const float*)d_in[5];
    const float* bv    = (const float*)d_in[6];
    const float* Wo    = (const float*)d_in[7];
    const float* bo    = (const float*)d_in[8];
    const float* g1    = (const float*)d_in[9];
    const float* beta1 = (const float*)d_in[10];
    const float* gateW = (const float*)d_in[11];
    const float* gateb = (const float*)d_in[12];
    const float* eW1   = (const float*)d_in[13];
    const float* eb1   = (const float*)d_in[14];
    const float* eW2   = (const float*)d_in[15];
    const float* eb2   = (const float*)d_in[16];
    const float* g2    = (const float*)d_in[17];
    const float* beta2 = (const float*)d_in[18];
    float* out = (float*)d_out;

    float *pQ, *pK, *pV, *pAO, *pP, *pX1, *pMoe, *pH, *pWgt;
    int *pCnt, *pIdx;
    cudaGetSymbolAddress((void**)&pQ,   g_Q);
    cudaGetSymbolAddress((void**)&pK,   g_Kb);
    cudaGetSymbolAddress((void**)&pV,   g_Vb);
    cudaGetSymbolAddress((void**)&pAO,  g_AO);
    cudaGetSymbolAddress((void**)&pP,   g_P);
    cudaGetSymbolAddress((void**)&pX1,  g_X1);
    cudaGetSymbolAddress((void**)&pMoe, g_moe);
    cudaGetSymbolAddress((void**)&pH,   g_H);
    cudaGetSymbolAddress((void**)&pCnt, g_cnt);
    cudaGetSymbolAddress((void**)&pIdx, g_eidx);
    cudaGetSymbolAddress((void**)&pWgt, g_ewgt);

    const int attn_smem = (2 * 64 * KP + 64 * VP) * (int)sizeof(uint32_t);  // 53248
    cudaFuncSetAttribute(attn_tc, cudaFuncAttributeMaxDynamicSharedMemorySize, attn_smem);

    zero_cnt_kernel<<<1, 32>>>();
    zero_moe_kernel<<<(Tc * Dc) / 1024, 256>>>();

    dim3 gD(Dc / 128, Tc / 128);   // (8, 64)
    gemm_tc<0,false><<<gD, 256>>>(x, Wq, bq, pQ, Tc, Dc, Dc, nullptr, nullptr, nullptr);
    gemm_tc<0,false><<<gD, 256>>>(x, Wk, bk, pK, Tc, Dc, Dc, nullptr, nullptr, nullptr);
    gemm_tc<0,false><<<gD, 256>>>(x, Wv, bv, pV, Tc, Dc, Dc, nullptr, nullptr, nullptr);

    attn_tc<<<dim3(Sc / 64, Bc * Hc), 128, attn_smem>>>(pQ, pK, pV, pAO);

    gemm_tc<0,false><<<gD, 256>>>(pAO, Wo, bo, pP, Tc, Dc, Dc, nullptr, nullptr, nullptr);
    add_ln_kernel<<<Tc, 256>>>(x, pP, g1, beta1, pX1);

    gate_kernel<<<Tc, 256>>>(pX1, gateW, gateb);

    dim3 gF(Fc / 128, Tc / 128);   // (32, 64)
    for (int e = 0; e < Ec; e++) {
        gemm_tc<1,true><<<gF, 256>>>(pX1, eW1 + (size_t)e * Dc * Fc, eb1 + e * Fc,
                                     pH, Tc, Fc, Dc,
                                     pIdx + e * Tc, nullptr, pCnt + e);
        gemm_tc<2,false><<<gD, 256>>>(pH, eW2 + (size_t)e * Fc * Dc, eb2 + e * Dc,
                                      pMoe, Tc, Dc, Fc,
                                      pIdx + e * Tc, pWgt + e * Tc, pCnt + e);
    }

    add_ln_kernel<<<Tc, 256>>>(pX1, pMoe, g2, beta2, out);
    aux_kernel<<<1, 256>>>(out + (size_t)Tc * Dc);
}

// round 11
// speedup vs baseline: 5.0812x; 1.3330x over previous
#include <cuda_runtime.h>
#include <cstdint>

#define Bc 4
#define Sc 2048
#define Dc 1024
#define Hc 16
#define HDc 64
#define Fc 4096
#define Ec 8
#define Kc 2
#define Tc (Bc*Sc)   /* 8192 */

// ---------------- scratch (static device globals; no allocation) ----------------
__device__ float g_Q[Tc*Dc];
__device__ float g_Kb[Tc*Dc];
__device__ float g_Vb[Tc*Dc];
__device__ uint32_t g_AOt[Tc*Dc];            // attention out, tiled tf32
__device__ float g_P[Tc*Dc];
__device__ float g_X1[Tc*Dc];
__device__ uint32_t g_X1t[Tc*Dc];            // X1, row-major tf32 (gather path)
__device__ float g_moe[Tc*Dc];
__device__ uint32_t g_Ht[(size_t)Tc*Fc];     // expert hidden, tiled tf32
__device__ uint32_t g_xt[Tc*Dc];             // x, tiled tf32
__device__ uint32_t g_Wt[4][Dc*Dc];          // Wq,Wk,Wv,Wo tf32
__device__ uint32_t g_eW1t[(size_t)Ec*Dc*Fc];
__device__ uint32_t g_eW2t[(size_t)Ec*Fc*Dc];
__device__ int   g_cnt[Ec];
__device__ int   g_eidx[Ec*Tc];
__device__ float g_ewgt[Ec*Tc];
__device__ float g_scores[Tc*Ec];

__device__ __forceinline__ float gelu_f(float v) {
    return 0.5f * v * (1.0f + erff(v * 0.70710678118654752f));
}
__device__ __forceinline__ uint32_t f2tf(float f) {
    uint32_t u; asm("cvt.rna.tf32.f32 %0, %1;" : "=r"(u) : "f"(f)); return u;
}
__device__ __forceinline__ void mma8(float4& d, const uint32_t* a, const uint32_t* b) {
    asm volatile(
        "mma.sync.aligned.m16n8k8.row.col.f32.tf32.tf32.f32 "
        "{%0,%1,%2,%3}, {%4,%5,%6,%7}, {%8,%9}, {%0,%1,%2,%3};\n"
        : "+f"(d.x), "+f"(d.y), "+f"(d.z), "+f"(d.w)
        : "r"(a[0]), "r"(a[1]), "r"(a[2]), "r"(a[3]), "r"(b[0]), "r"(b[1]));
}

// cp.async helpers
#define CPA16(dst, src) \
    asm volatile("cp.async.cg.shared.global [%0], [%1], 16;" :: "r"(dst), "l"(src))
#define CPA16Z(dst, src, sz) \
    asm volatile("cp.async.cg.shared.global [%0], [%1], 16, %2;" :: "r"(dst), "l"(src), "r"(sz))
#define CPA_COMMIT() asm volatile("cp.async.commit_group;")
#define CPA_WAIT0()  asm volatile("cp.async.wait_group 0;")

// ---- fragment-major A tile layout: tile = 128 rows x 32 k = 4096 u32 (16KB) ----
// within tile: uint4 index (ks*8 + mgrp)*32 + (g*4+tg); regs = (A[g][tg],A[g+8][tg],A[g][tg+4],A[g+8][tg+4])
__device__ __forceinline__ int a_elem_off(int mloc, int kloc) {
    int mgrp = mloc >> 4, g = mloc & 7, r8 = (mloc >> 3) & 1;
    int ks = kloc >> 3, tg = kloc & 3, khalf = (kloc >> 2) & 1;
    return (((ks * 8 + mgrp) * 32) + (g * 4 + tg)) * 4 + (khalf * 2 + r8);
}

// ---------------- conversion kernels ----------------
__global__ void __launch_bounds__(256) conv_plain(const float* __restrict__ in,
                                                  uint32_t* __restrict__ out, size_t n4)
{
    size_t i = (size_t)blockIdx.x * 256 + threadIdx.x;
    size_t stride = (size_t)gridDim.x * 256;
    for (; i < n4; i += stride) {
        float4 v = ((const float4*)in)[i];
        ((uint4*)out)[i] = make_uint4(f2tf(v.x), f2tf(v.y), f2tf(v.z), f2tf(v.w));
    }
}

// row-major [M,K] fp32 -> tiled-fragment tf32 ; grid (K/32, M/128), 256 thr
__global__ void __launch_bounds__(256) conv_tiled(const float* __restrict__ in,
                                                  uint32_t* __restrict__ out, int K)
{
    int kt = blockIdx.x, mt = blockIdx.y;
    int nkt = K >> 5;
    size_t tb = ((size_t)mt * nkt + kt) * 4096;
    int tid = threadIdx.x;
#pragma unroll
    for (int j = 0; j < 4; j++) {
        int c = tid + j * 256;
        int mloc = c >> 3, kc = c & 7;
        float4 v = *(const float4*)(in + (size_t)(mt * 128 + mloc) * K + kt * 32 + kc * 4);
        out[tb + a_elem_off(mloc, kc * 4 + 0)] = f2tf(v.x);
        out[tb + a_elem_off(mloc, kc * 4 + 1)] = f2tf(v.y);
        out[tb + a_elem_off(mloc, kc * 4 + 2)] = f2tf(v.z);
        out[tb + a_elem_off(mloc, kc * 4 + 3)] = f2tf(v.w);
    }
}

// ======== GEMM, A in tiled-fragment tf32 (cp.async verbatim), B row-major tf32 ========
// Tile 128x128, BK=32, 256 thr (8 warps 2x4), warp 64x32.
// MODE 0: C = acc+bias ; MODE 2: C[rowidx[m]] += roww[m]*(acc+bias)
#define BSP 136
template<int MODE>
__global__ void __launch_bounds__(256, 2) gemm_tcA(
    const uint32_t* __restrict__ At, const uint32_t* __restrict__ Bt,
    const float* __restrict__ bias, float* __restrict__ C,
    int N, int Kd, int nkt,
    const int* __restrict__ rowidx, const float* __restrict__ roww,
    const int* __restrict__ Mcnt, int Mtot)
{
    extern __shared__ uint32_t sm[];
    uint32_t* As = sm;                   // [2][4096]
    uint32_t* Bs = sm + 8192;            // [2][32*BSP]

    int Meff = Mcnt ? *Mcnt : Mtot;
    int m0 = blockIdx.y * 128;
    if (m0 >= Meff) return;
    int n0 = blockIdx.x * 128;

    int tid = threadIdx.x;
    int wid = tid >> 5, lane = tid & 31;
    int wrow = wid >> 2, wn = (wid & 3) * 32;
    int g = lane >> 2, tg = lane & 3;
    int aidx = g * 4 + tg;

    uint32_t sA = (uint32_t)__cvta_generic_to_shared(As);
    uint32_t sB = (uint32_t)__cvta_generic_to_shared(Bs);

    float4 acc[4][4];
#pragma unroll
    for (int i = 0; i < 4; i++)
#pragma unroll
        for (int j = 0; j < 4; j++) acc[i][j] = make_float4(0.f, 0.f, 0.f, 0.f);

    int nk = Kd >> 5;
    size_t abase = (size_t)blockIdx.y * nkt * 4096;

    // issue tile 0
    {
        const uint32_t* at = At + abase;
#pragma unroll
        for (int j = 0; j < 4; j++) {
            int c = tid + j * 256;
            CPA16(sA + c * 16, at + c * 4);
        }
#pragma unroll
        for (int j = 0; j < 4; j++) {
            int c = tid + j * 256;
            int row = c >> 5, nc = c & 31;
            CPA16(sB + (row * BSP + nc * 4) * 4, Bt + (size_t)row * N + n0 + nc * 4);
        }
        CPA_COMMIT();
    }

    for (int i = 0; i < nk; i++) {
        int buf = i & 1;
        CPA_WAIT0();
        __syncthreads();
        if (i + 1 < nk) {
            int nb = buf ^ 1;
            const uint32_t* at = At + abase + (size_t)(i + 1) * 4096;
            int k0 = (i + 1) << 5;
#pragma unroll
            for (int j = 0; j < 4; j++) {
                int c = tid + j * 256;
                CPA16(sA + (nb * 4096 + c * 4) * 4, at + c * 4);
            }
#pragma unroll
            for (int j = 0; j < 4; j++) {
                int c = tid + j * 256;
                int row = c >> 5, nc = c & 31;
                CPA16(sB + ((nb * 32 + row) * BSP + nc * 4) * 4,
                      Bt + (size_t)(k0 + row) * N + n0 + nc * 4);
            }
            CPA_COMMIT();
        }

        const uint4* Ab = (const uint4*)(As + buf * 4096);
        const uint32_t* Bb = Bs + buf * 32 * BSP;
#pragma unroll
        for (int ks = 0; ks < 4; ks++) {
            uint4 af4[4];
#pragma unroll
            for (int i2 = 0; i2 < 4; i2++)
                af4[i2] = Ab[(ks * 8 + wrow * 4 + i2) * 32 + aidx];
            uint32_t bfr[4][2];
#pragma unroll
            for (int j = 0; j < 4; j++) {
                bfr[j][0] = Bb[(ks * 8 + tg) * BSP + wn + j * 8 + g];
                bfr[j][1] = Bb[(ks * 8 + 4 + tg) * BSP + wn + j * 8 + g];
            }
#pragma unroll
            for (int i2 = 0; i2 < 4; i2++)
#pragma unroll
                for (int j = 0; j < 4; j++)
                    mma8(acc[i2][j], (const uint32_t*)&af4[i2], bfr[j]);
        }
        __syncthreads();
    }

#pragma unroll
    for (int i = 0; i < 4; i++) {
#pragma unroll
        for (int half = 0; half < 2; half++) {
            int m = m0 + wrow * 64 + i * 16 + g + half * 8;
            if (m >= Meff) continue;
            int crow = m;
            float w = 1.f;
            if (MODE == 2) { crow = rowidx[m]; w = roww[m]; }
            float* cp = C + (size_t)crow * N;
#pragma unroll
            for (int j = 0; j < 4; j++) {
                int c = n0 + wn + j * 8 + tg * 2;
                float2 bp = *(const float2*)(bias + c);
                float u0 = (half ? acc[i][j].z : acc[i][j].x) + bp.x;
                float u1 = (half ? acc[i][j].w : acc[i][j].y) + bp.y;
                if (MODE == 2) {
                    float2 old = *(float2*)(cp + c);
                    old.x += w * u0; old.y += w * u1;
                    *(float2*)(cp + c) = old;
                } else {
                    *(float2*)(cp + c) = make_float2(u0, u1);
                }
            }
        }
    }
}

// ======== gathered GEMM (expert W1): A row-major tf32 gathered, gelu -> tiled H ========
#define ASP 36
__global__ void __launch_bounds__(256, 2) gemm_gather(
    const uint32_t* __restrict__ At, const uint32_t* __restrict__ Bt,
    const float* __restrict__ bias, uint32_t* __restrict__ Ht,
    int N, int Kd,
    const int* __restrict__ rowidx, const int* __restrict__ Mcnt)
{
    extern __shared__ uint32_t sm[];
    uint32_t* As = sm;                    // [2][128*ASP]
    uint32_t* Bs = sm + 2 * 128 * ASP;    // [2][32*BSP]

    int Meff = *Mcnt;
    int m0 = blockIdx.y * 128;
    if (m0 >= Meff) return;
    int n0 = blockIdx.x * 128;

    int tid = threadIdx.x;
    int wid = tid >> 5, lane = tid & 31;
    int wrow = wid >> 2, wn = (wid & 3) * 32;
    int g = lane >> 2, tg = lane & 3;
    int wm = wrow * 64;

    uint32_t sA = (uint32_t)__cvta_generic_to_shared(As);
    uint32_t sB = (uint32_t)__cvta_generic_to_shared(Bs);

    // gather row setup: thread j-th chunk covers row (tid>>3)+j*32, k-chunk (tid&7)
    int amr = tid >> 3, ack = tid & 7;
    int ga[4]; uint32_t asz[4];
#pragma unroll
    for (int j = 0; j < 4; j++) {
        int m = m0 + amr + j * 32;
        bool ok = m < Meff;
        ga[j] = ok ? rowidx[m] : 0;
        asz[j] = ok ? 16u : 0u;
    }

    float4 acc[4][4];
#pragma unroll
    for (int i = 0; i < 4; i++)
#pragma unroll
        for (int j = 0; j < 4; j++) acc[i][j] = make_float4(0.f, 0.f, 0.f, 0.f);

    int nk = Kd >> 5;

    {
#pragma unroll
        for (int j = 0; j < 4; j++) {
            int m = amr + j * 32;
            CPA16Z(sA + (m * ASP + ack * 4) * 4, At + (size_t)ga[j] * Kd + ack * 4, asz[j]);
        }
#pragma unroll
        for (int j = 0; j < 4; j++) {
            int c = tid + j * 256;
            int row = c >> 5, nc = c & 31;
            CPA16(sB + (row * BSP + nc * 4) * 4, Bt + (size_t)row * N + n0 + nc * 4);
        }
        CPA_COMMIT();
    }

    for (int i = 0; i < nk; i++) {
        int buf = i & 1;
        CPA_WAIT0();
        __syncthreads();
        if (i + 1 < nk) {
            int nb = buf ^ 1;
            int k0 = (i + 1) << 5;
#pragma unroll
            for (int j = 0; j < 4; j++) {
                int m = amr + j * 32;
                CPA16Z(sA + ((nb * 128 + m) * ASP + ack * 4) * 4,
                       At + (size_t)ga[j] * Kd + k0 + ack * 4, asz[j]);
            }
#pragma unroll
            for (int j = 0; j < 4; j++) {
                int c = tid + j * 256;
                int row = c >> 5, nc = c & 31;
                CPA16(sB + ((nb * 32 + row) * BSP + nc * 4) * 4,
                      Bt + (size_t)(k0 + row) * N + n0 + nc * 4);
            }
            CPA_COMMIT();
        }

        const uint32_t* Ab = As + buf * 128 * ASP;
        const uint32_t* Bb = Bs + buf * 32 * BSP;
#pragma unroll
        for (int ks = 0; ks < 4; ks++) {
            uint32_t af[4][4];
#pragma unroll
            for (int i2 = 0; i2 < 4; i2++) {
                int r0 = wm + i2 * 16 + g, r1 = r0 + 8;
                af[i2][0] = Ab[r0 * ASP + ks * 8 + tg];
                af[i2][1] = Ab[r1 * ASP + ks * 8 + tg];
                af[i2][2] = Ab[r0 * ASP + ks * 8 + 4 + tg];
                af[i2][3] = Ab[r1 * ASP + ks * 8 + 4 + tg];
            }
            uint32_t bfr[4][2];
#pragma unroll
            for (int j = 0; j < 4; j++) {
                bfr[j][0] = Bb[(ks * 8 + tg) * BSP + wn + j * 8 + g];
                bfr[j][1] = Bb[(ks * 8 + 4 + tg) * BSP + wn + j * 8 + g];
            }
#pragma unroll
            for (int i2 = 0; i2 < 4; i2++)
#pragma unroll
                for (int j = 0; j < 4; j++)
                    mma8(acc[i2][j], af[i2], bfr[j]);
        }
        __syncthreads();
    }

    // epilogue: gelu, write tiled-fragment tf32 H  (nkt = N/32)
    int nktH = N >> 5;
#pragma unroll
    for (int i = 0; i < 4; i++) {
#pragma unroll
        for (int half = 0; half < 2; half++) {
            int m = m0 + wm + i * 16 + g + half * 8;
            if (m >= Meff) continue;
            size_t rowtb = (size_t)(m >> 7) * nktH;
            int mloc = m & 127;
#pragma unroll
            for (int j = 0; j < 4; j++) {
                int c = n0 + wn + j * 8 + tg * 2;
                float2 bp = *(const float2*)(bias + c);
                float u0 = gelu_f((half ? acc[i][j].z : acc[i][j].x) + bp.x);
                float u1 = gelu_f((half ? acc[i][j].w : acc[i][j].y) + bp.y);
                size_t tb = (rowtb + (c >> 5)) * 4096;
                Ht[tb + a_elem_off(mloc, c & 31)]       = f2tf(u0);
                Ht[tb + a_elem_off(mloc, (c + 1) & 31)] = f2tf(u1);
            }
        }
    }
}

// ---------------- flash attention, tf32 mma, epilogue -> tiled tf32 AO ----------------
#define KP 68
#define VP 72
__global__ void __launch_bounds__(128) attn_tc(
    const float* __restrict__ Q, const float* __restrict__ Kin,
    const float* __restrict__ Vin, uint32_t* __restrict__ AOt)
{
    extern __shared__ uint32_t smx[];
    uint32_t* Ks = smx;
    uint32_t* Ps = smx + 64 * KP;
    uint32_t* Vs = smx + 2 * 64 * KP;

    int bh = blockIdx.y;
    int b = bh >> 4, h = bh & 15;
    int q0 = blockIdx.x * 64;
    int tid = threadIdx.x;
    int wid = tid >> 5, lane = tid & 31;
    int g = lane >> 2, tg = lane & 3;
    int w16 = wid * 16;
    size_t base = (size_t)(b * Sc) * Dc + h * 64;
    const unsigned fullm = 0xffffffffu;

#pragma unroll
    for (int j = 0; j < 8; j++) {
        int idx = tid + j * 128;
        int r = idx >> 4, c = (idx & 15) * 4;
        float4 q4 = *(const float4*)(Q + base + (size_t)(q0 + r) * Dc + c);
        *(uint4*)&Ks[r * KP + c] = make_uint4(f2tf(q4.x), f2tf(q4.y), f2tf(q4.z), f2tf(q4.w));
    }
    __syncthreads();
    uint32_t qf[8][4];
#pragma unroll
    for (int d0 = 0; d0 < 8; d0++) {
        qf[d0][0] = Ks[(w16 + g) * KP + d0 * 8 + tg];
        qf[d0][1] = Ks[(w16 + 8 + g) * KP + d0 * 8 + tg];
        qf[d0][2] = Ks[(w16 + g) * KP + d0 * 8 + 4 + tg];
        qf[d0][3] = Ks[(w16 + 8 + g) * KP + d0 * 8 + 4 + tg];
    }

    float m0r = -1e30f, m1r = -1e30f;
    float l0r = 0.f, l1r = 0.f;
    float4 of[8];
#pragma unroll
    for (int j = 0; j < 8; j++) of[j] = make_float4(0.f, 0.f, 0.f, 0.f);

    for (int kv0 = 0; kv0 < Sc; kv0 += 64) {
        __syncthreads();
#pragma unroll
        for (int j = 0; j < 8; j++) {
            int idx = tid + j * 128;
            int r = idx >> 4, c = (idx & 15) * 4;
            float4 k4 = *(const float4*)(Kin + base + (size_t)(kv0 + r) * Dc + c);
            float4 v4 = *(const float4*)(Vin + base + (size_t)(kv0 + r) * Dc + c);
            *(uint4*)&Ks[r * KP + c] = make_uint4(f2tf(k4.x), f2tf(k4.y), f2tf(k4.z), f2tf(k4.w));
            *(uint4*)&Vs[r * VP + c] = make_uint4(f2tf(v4.x), f2tf(v4.y), f2tf(v4.z), f2tf(v4.w));
        }
        __syncthreads();

        float4 sa[8];
#pragma unroll
        for (int j = 0; j < 8; j++) sa[j] = make_float4(0.f, 0.f, 0.f, 0.f);
#pragma unroll
        for (int d0 = 0; d0 < 8; d0++) {
#pragma unroll
            for (int j = 0; j < 8; j++) {
                uint32_t bf[2];
                bf[0] = Ks[(j * 8 + g) * KP + d0 * 8 + tg];
                bf[1] = Ks[(j * 8 + g) * KP + d0 * 8 + 4 + tg];
                mma8(sa[j], qf[d0], bf);
            }
        }

        float t0 = -1e30f, t1 = -1e30f;
#pragma unroll
        for (int j = 0; j < 8; j++) {
            sa[j].x *= 0.125f; sa[j].y *= 0.125f; sa[j].z *= 0.125f; sa[j].w *= 0.125f;
            t0 = fmaxf(t0, fmaxf(sa[j].x, sa[j].y));
            t1 = fmaxf(t1, fmaxf(sa[j].z, sa[j].w));
        }
        t0 = fmaxf(t0, __shfl_xor_sync(fullm, t0, 1));
        t0 = fmaxf(t0, __shfl_xor_sync(fullm, t0, 2));
        t1 = fmaxf(t1, __shfl_xor_sync(fullm, t1, 1));
        t1 = fmaxf(t1, __shfl_xor_sync(fullm, t1, 2));
        float mn0 = fmaxf(m0r, t0), mn1 = fmaxf(m1r, t1);
        float al0 = __expf(m0r - mn0), al1 = __expf(m1r - mn1);
        float rs0 = 0.f, rs1 = 0.f;
#pragma unroll
        for (int j = 0; j < 8; j++) {
            sa[j].x = __expf(sa[j].x - mn0); sa[j].y = __expf(sa[j].y - mn0);
            sa[j].z = __expf(sa[j].z - mn1); sa[j].w = __expf(sa[j].w - mn1);
            rs0 += sa[j].x + sa[j].y; rs1 += sa[j].z + sa[j].w;
        }
        rs0 += __shfl_xor_sync(fullm, rs0, 1); rs0 += __shfl_xor_sync(fullm, rs0, 2);
        rs1 += __shfl_xor_sync(fullm, rs1, 1); rs1 += __shfl_xor_sync(fullm, rs1, 2);
        l0r = l0r * al0 + rs0; l1r = l1r * al1 + rs1;
        m0r = mn0; m1r = mn1;
#pragma unroll
        for (int j = 0; j < 8; j++) {
            of[j].x *= al0; of[j].y *= al0; of[j].z *= al1; of[j].w *= al1;
        }

#pragma unroll
        for (int j = 0; j < 8; j++) {
            int col = j * 8 + tg * 2;
            Ps[(w16 + g) * KP + col]     = f2tf(sa[j].x);
            Ps[(w16 + g) * KP + col + 1] = f2tf(sa[j].y);
            Ps[(w16 + 8 + g) * KP + col]     = f2tf(sa[j].z);
            Ps[(w16 + 8 + g) * KP + col + 1] = f2tf(sa[j].w);
        }
        __syncwarp();

#pragma unroll
        for (int k0 = 0; k0 < 8; k0++) {
            uint32_t af[4];
            af[0] = Ps[(w16 + g) * KP + k0 * 8 + tg];
            af[1] = Ps[(w16 + 8 + g) * KP + k0 * 8 + tg];
            af[2] = Ps[(w16 + g) * KP + k0 * 8 + 4 + tg];
            af[3] = Ps[(w16 + 8 + g) * KP + k0 * 8 + 4 + tg];
#pragma unroll
            for (int j = 0; j < 8; j++) {
                uint32_t bf[2];
                bf[0] = Vs[(k0 * 8 + tg) * VP + j * 8 + g];
                bf[1] = Vs[(k0 * 8 + 4 + tg) * VP + j * 8 + g];
                mma8(of[j], af, bf);
            }
        }
    }

    // epilogue -> tiled-fragment tf32 AO (nkt = Dc/32 = 32)
    float inv0 = 1.f / l0r, inv1 = 1.f / l1r;
    int mg0 = b * Sc + q0 + w16 + g;
    int mg1 = mg0 + 8;
    size_t rtb0 = (size_t)(mg0 >> 7) * 32;
    size_t rtb1 = (size_t)(mg1 >> 7) * 32;
    int ml0 = mg0 & 127, ml1 = mg1 & 127;
#pragma unroll
    for (int j = 0; j < 8; j++) {
        int col = h * 64 + j * 8 + tg * 2;
        size_t tb0 = (rtb0 + (col >> 5)) * 4096;
        size_t tb1 = (rtb1 + (col >> 5)) * 4096;
        AOt[tb0 + a_elem_off(ml0, col & 31)]       = f2tf(of[j].x * inv0);
        AOt[tb0 + a_elem_off(ml0, (col + 1) & 31)] = f2tf(of[j].y * inv0);
        AOt[tb1 + a_elem_off(ml1, col & 31)]       = f2tf(of[j].z * inv1);
        AOt[tb1 + a_elem_off(ml1, (col + 1) & 31)] = f2tf(of[j].w * inv1);
    }
}

// ---------------- residual + layernorm (optional tf32 row-major copy) ----------------
__global__ void __launch_bounds__(256) add_ln_kernel(
    const float* __restrict__ xin, const float* __restrict__ res,
    const float* __restrict__ g, const float* __restrict__ bta,
    float* __restrict__ out, uint32_t* __restrict__ outt)
{
    int t = blockIdx.x;
    int tid = threadIdx.x;
    const float4 xv = ((const float4*)(xin + (size_t)t * Dc))[tid];
    const float4 rv = ((const float4*)(res + (size_t)t * Dc))[tid];
    float v[4] = {xv.x + rv.x, xv.y + rv.y, xv.z + rv.z, xv.w + rv.w};
    float s  = v[0] + v[1] + v[2] + v[3];
    float sq = v[0]*v[0] + v[1]*v[1] + v[2]*v[2] + v[3]*v[3];
#pragma unroll
    for (int off = 16; off; off >>= 1) {
        s  += __shfl_xor_sync(0xffffffffu, s, off);
        sq += __shfl_xor_sync(0xffffffffu, sq, off);
    }
    __shared__ float ss[8], qq[8];
    __shared__ float smu, srstd;
    int wid = tid >> 5;
    if ((tid & 31) == 0) { ss[wid] = s; qq[wid] = sq; }
    __syncthreads();
    if (tid == 0) {
        float ts = 0.f, tq = 0.f;
#pragma unroll
        for (int i = 0; i < 8; i++) { ts += ss[i]; tq += qq[i]; }
        float mu = ts / (float)Dc;
        float var = tq / (float)Dc - mu * mu;
        smu = mu; srstd = rsqrtf(var + 1e-5f);
    }
    __syncthreads();
    float mu = smu, rstd = srstd;
    float4 g4 = ((const float4*)g)[tid];
    float4 b4 = ((const float4*)bta)[tid];
    float4 o4;
    o4.x = (v[0]-mu)*rstd*g4.x + b4.x;
    o4.y = (v[1]-mu)*rstd*g4.y + b4.y;
    o4.z = (v[2]-mu)*rstd*g4.z + b4.z;
    o4.w = (v[3]-mu)*rstd*g4.w + b4.w;
    ((float4*)(out + (size_t)t * Dc))[tid] = o4;
    if (outt)
        ((uint4*)(outt + (size_t)t * Dc))[tid] =
            make_uint4(f2tf(o4.x), f2tf(o4.y), f2tf(o4.z), f2tf(o4.w));
}

// ---------------- gate ----------------
__global__ void __launch_bounds__(256) gate_kernel(
    const float* __restrict__ x1, const float* __restrict__ gW,
    const float* __restrict__ gb)
{
    int t = blockIdx.x;
    int tid = threadIdx.x;
    float part[Ec];
#pragma unroll
    for (int e = 0; e < Ec; e++) part[e] = 0.f;
    const float* xr = x1 + (size_t)t * Dc;
    for (int d = tid; d < Dc; d += 256) {
        float xv = xr[d];
        const float* wr = gW + d * Ec;
#pragma unroll
        for (int e = 0; e < Ec; e++) part[e] += xv * wr[e];
    }
    __shared__ float sm[Ec][264];
#pragma unroll
    for (int e = 0; e < Ec; e++) sm[e][tid] = part[e];
    __syncthreads();
    for (int off = 128; off; off >>= 1) {
        if (tid < off) {
#pragma unroll
            for (int e = 0; e < Ec; e++) sm[e][tid] += sm[e][tid + off];
        }
        __syncthreads();
    }
    if (tid == 0) {
        float lg[Ec], sc[Ec];
        float m = -1e30f;
#pragma unroll
        for (int e = 0; e < Ec; e++) { lg[e] = sm[e][0] + gb[e]; m = fmaxf(m, lg[e]); }
        float sum = 0.f;
#pragma unroll
        for (int e = 0; e < Ec; e++) { sc[e] = expf(lg[e] - m); sum += sc[e]; }
        float inv = 1.f / sum;
#pragma unroll
        for (int e = 0; e < Ec; e++) { sc[e] *= inv; g_scores[t * Ec + e] = sc[e]; }
        int a1 = 0;
#pragma unroll
        for (int e = 1; e < Ec; e++) if (sc[e] > sc[a1]) a1 = e;
        int a2 = (a1 == 0) ? 1 : 0;
#pragma unroll
        for (int e = 0; e < Ec; e++) if (e != a1 && sc[e] > sc[a2]) a2 = e;
        float ws = sc[a1] + sc[a2];
        float w1 = sc[a1] / ws, w2 = sc[a2] / ws;
        int p1 = atomicAdd(&g_cnt[a1], 1);
        g_eidx[a1 * Tc + p1] = t; g_ewgt[a1 * Tc + p1] = w1;
        int p2 = atomicAdd(&g_cnt[a2], 1);
        g_eidx[a2 * Tc + p2] = t; g_ewgt[a2 * Tc + p2] = w2;
    }
}

// ---------------- aux loss ----------------
__global__ void __launch_bounds__(256) aux_kernel(float* __restrict__ out)
{
    int tid = threadIdx.x;
    float part[Ec];
#pragma unroll
    for (int e = 0; e < Ec; e++) part[e] = 0.f;
    for (int t = tid; t < Tc; t += 256) {
#pragma unroll
        for (int e = 0; e < Ec; e++) part[e] += g_scores[t * Ec + e];
    }
    __shared__ float sm[Ec][264];
#pragma unroll
    for (int e = 0; e < Ec; e++) sm[e][tid] = part[e];
    __syncthreads();
    for (int off = 128; off; off >>= 1) {
        if (tid < off) {
#pragma unroll
            for (int e = 0; e < Ec; e++) sm[e][tid] += sm[e][tid + off];
        }
        __syncthreads();
    }
    if (tid == 0) {
        float aux = 0.f;
#pragma unroll
        for (int e = 0; e < Ec; e++) {
            float ef = (float)g_cnt[e] / (float)(Tc * Kc);
            float rw = sm[e][0] / (float)Tc;
            aux += ef * rw;
        }
        out[0] = aux * (float)Ec;
    }
}

// ---------------- state reset ----------------
__global__ void zero_cnt_kernel() {
    if (threadIdx.x < Ec) g_cnt[threadIdx.x] = 0;
}
__global__ void zero_moe_kernel() {
    size_t i = ((size_t)blockIdx.x * 256 + threadIdx.x) * 4;
    *(float4*)(g_moe + i) = make_float4(0.f, 0.f, 0.f, 0.f);
}

// ---------------- launch ----------------
extern "C" void kernel_launch(void* const* d_in, const int* in_sizes, int n_in,
                              void* d_out, int out_size)
{
    (void)in_sizes; (void)n_in; (void)out_size;
    const float* x     = (const float*)d_in[0];
    const float* Wq    = (const float*)d_in[1];
    const float* bq    = (const float*)d_in[2];
    const float* Wk    = (const float*)d_in[3];
    const float* bk    = (const float*)d_in[4];
    const float* Wv    = (const float*)d_in[5];
    const float* bv    = (const float*)d_in[6];
    const float* Wo    = (const float*)d_in[7];
    const float* bo    = (const float*)d_in[8];
    const float* g1    = (const float*)d_in[9];
    const float* beta1 = (const float*)d_in[10];
    const float* gateW = (const float*)d_in[11];
    const float* gateb = (const float*)d_in[12];
    const float* eW1   = (const float*)d_in[13];
    const float* eb1   = (const float*)d_in[14];
    const float* eW2   = (const float*)d_in[15];
    const float* eb2   = (const float*)d_in[16];
    const float* g2    = (const float*)d_in[17];
    const float* beta2 = (const float*)d_in[18];
    float* out = (float*)d_out;

    float *pQ, *pK, *pV, *pP, *pX1, *pMoe, *pWgt;
    uint32_t *pAOt, *pX1t, *pHt, *pxt, *pWt, *peW1t, *peW2t;
    int *pCnt, *pIdx;
    cudaGetSymbolAddress((void**)&pQ,    g_Q);
    cudaGetSymbolAddress((void**)&pK,    g_Kb);
    cudaGetSymbolAddress((void**)&pV,    g_Vb);
    cudaGetSymbolAddress((void**)&pAOt,  g_AOt);
    cudaGetSymbolAddress((void**)&pP,    g_P);
    cudaGetSymbolAddress((void**)&pX1,   g_X1);
    cudaGetSymbolAddress((void**)&pX1t,  g_X1t);
    cudaGetSymbolAddress((void**)&pMoe,  g_moe);
    cudaGetSymbolAddress((void**)&pHt,   g_Ht);
    cudaGetSymbolAddress((void**)&pxt,   g_xt);
    cudaGetSymbolAddress((void**)&pWt,   g_Wt);
    cudaGetSymbolAddress((void**)&peW1t, g_eW1t);
    cudaGetSymbolAddress((void**)&peW2t, g_eW2t);
    cudaGetSymbolAddress((void**)&pCnt,  g_cnt);
    cudaGetSymbolAddress((void**)&pIdx,  g_eidx);
    cudaGetSymbolAddress((void**)&pWgt,  g_ewgt);

    const int attn_smem = (2 * 64 * KP + 64 * VP) * (int)sizeof(uint32_t);      // 53248
    const int gA_smem = (2 * 4096 + 2 * 32 * BSP) * (int)sizeof(uint32_t);      // 67584
    const int gG_smem = (2 * 128 * ASP + 2 * 32 * BSP) * (int)sizeof(uint32_t); // 71680
    cudaFuncSetAttribute(attn_tc, cudaFuncAttributeMaxDynamicSharedMemorySize, attn_smem);
    cudaFuncSetAttribute(gemm_tcA<0>, cudaFuncAttributeMaxDynamicSharedMemorySize, gA_smem);
    cudaFuncSetAttribute(gemm_tcA<2>, cudaFuncAttributeMaxDynamicSharedMemorySize, gA_smem);
    cudaFuncSetAttribute(gemm_gather, cudaFuncAttributeMaxDynamicSharedMemorySize, gG_smem);

    zero_cnt_kernel<<<1, 32>>>();
    zero_moe_kernel<<<(Tc * Dc) / 1024, 256>>>();

    // conversions (re-run every replay; deterministic)
    conv_tiled<<<dim3(Dc / 32, Tc / 128), 256>>>(x, pxt, Dc);
    conv_plain<<<512, 256>>>(Wq, pWt + 0 * (size_t)Dc * Dc, (size_t)Dc * Dc / 4);
    conv_plain<<<512, 256>>>(Wk, pWt + 1 * (size_t)Dc * Dc, (size_t)Dc * Dc / 4);
    conv_plain<<<512, 256>>>(Wv, pWt + 2 * (size_t)Dc * Dc, (size_t)Dc * Dc / 4);
    conv_plain<<<512, 256>>>(Wo, pWt + 3 * (size_t)Dc * Dc, (size_t)Dc * Dc / 4);
    conv_plain<<<2048, 256>>>(eW1, peW1t, (size_t)Ec * Dc * Fc / 4);
    conv_plain<<<2048, 256>>>(eW2, peW2t, (size_t)Ec * Fc * Dc / 4);

    dim3 gD(Dc / 128, Tc / 128);   // (8, 64)
    gemm_tcA<0><<<gD, 256, gA_smem>>>(pxt, pWt + 0 * (size_t)Dc * Dc, bq, pQ,
                                      Dc, Dc, Dc / 32, nullptr, nullptr, nullptr, Tc);
    gemm_tcA<0><<<gD, 256, gA_smem>>>(pxt, pWt + 1 * (size_t)Dc * Dc, bk, pK,
                                      Dc, Dc, Dc / 32, nullptr, nullptr, nullptr, Tc);
    gemm_tcA<0><<<gD, 256, gA_smem>>>(pxt, pWt + 2 * (size_t)Dc * Dc, bv, pV,
                                      Dc, Dc, Dc / 32, nullptr, nullptr, nullptr, Tc);

    attn_tc<<<dim3(Sc / 64, Bc * Hc), 128, attn_smem>>>(pQ, pK, pV, pAOt);

    gemm_tcA<0><<<gD, 256, gA_smem>>>(pAOt, pWt + 3 * (size_t)Dc * Dc, bo, pP,
                                      Dc, Dc, Dc / 32, nullptr, nullptr, nullptr, Tc);
    add_ln_kernel<<<Tc, 256>>>(x, pP, g1, beta1, pX1, pX1t);

    gate_kernel<<<Tc, 256>>>(pX1, gateW, gateb);

    dim3 gF(Fc / 128, Tc / 128);   // (32, 64)
    for (int e = 0; e < Ec; e++) {
        gemm_gather<<<gF, 256, gG_smem>>>(pX1t, peW1t + (size_t)e * Dc * Fc, eb1 + e * Fc,
                                          pHt, Fc, Dc, pIdx + e * Tc, pCnt + e);
        gemm_tcA<2><<<gD, 256, gA_smem>>>(pHt, peW2t + (size_t)e * Fc * Dc, eb2 + e * Dc,
                                          pMoe, Dc, Fc, Fc / 32,
                                          pIdx + e * Tc, pWgt + e * Tc, pCnt + e, Tc);
    }

    add_ln_kernel<<<Tc, 256>>>(pX1, pMoe, g2, beta2, out, nullptr);
    aux_kernel<<<1, 256>>>(out + (size_t)Tc * Dc);
}

// round 15
// speedup vs baseline: 7.3494x; 1.4464x over previous
#include <cuda_runtime.h>
#include <cuda_fp16.h>
#include <cstdint>

#define Bc 4
#define Sc 2048
#define Dc 1024
#define Hc 16
#define HDc 64
#define Fc 4096
#define Ec 8
#define Kc 2
#define Tc (Bc*Sc)   /* 8192 */

// ---------------- scratch (static device globals; no allocation) ----------------
__device__ uint32_t g_xt[Tc*Dc];              // x, tiled tf32
__device__ uint32_t g_Wt[4][Dc*Dc];           // Wq,Wk,Wv,Wo tf32
__device__ float    g_Q[Tc*Dc];
__device__ float    g_Kb[Tc*Dc];
__device__ float    g_Vb[Tc*Dc];
__device__ uint32_t g_AOt[Tc*Dc];             // attention out, tiled tf32
__device__ float    g_P[Tc*Dc];
__device__ float    g_X1[Tc*Dc];
__device__ uint32_t g_X1h[Tc*Dc/2];           // X1, row-major fp16 pairs (MoE gather)
__device__ float    g_moe[Tc*Dc];
__device__ uint32_t g_Ht[(size_t)Tc*Fc/2];    // expert hidden, fragment-tiled fp16
__device__ uint32_t g_eW1T[(size_t)Ec*Dc*Fc/2];   // fp16 transposed [N][K/2]
__device__ uint32_t g_eW2T[(size_t)Ec*Fc*Dc/2];
__device__ int   g_cnt[Ec];
__device__ int   g_eidx[Ec*Tc];
__device__ float g_ewgt[Ec*Tc];
__device__ float g_scores[Tc*Ec];

__device__ __forceinline__ float gelu_f(float v) {
    return 0.5f * v * (1.0f + erff(v * 0.70710678118654752f));
}
__device__ __forceinline__ uint32_t f2tf(float f) {
    uint32_t u; asm("cvt.rna.tf32.f32 %0, %1;" : "=r"(u) : "f"(f)); return u;
}
__device__ __forceinline__ uint32_t f2h2(float lo, float hi) {
    __half2 h = __floats2half2_rn(lo, hi);
    return *reinterpret_cast<uint32_t*>(&h);
}
// tf32: D += A(16x8) * B(8x8)
__device__ __forceinline__ void mma8(float4& d, const uint32_t* a, const uint32_t* b) {
    asm volatile(
        "mma.sync.aligned.m16n8k8.row.col.f32.tf32.tf32.f32 "
        "{%0,%1,%2,%3}, {%4,%5,%6,%7}, {%8,%9}, {%0,%1,%2,%3};\n"
        : "+f"(d.x), "+f"(d.y), "+f"(d.z), "+f"(d.w)
        : "r"(a[0]), "r"(a[1]), "r"(a[2]), "r"(a[3]), "r"(b[0]), "r"(b[1]));
}
// fp16: D += A(16x16) * B(16x8)
__device__ __forceinline__ void mma16(float4& d, const uint32_t* a, const uint32_t* b) {
    asm volatile(
        "mma.sync.aligned.m16n8k16.row.col.f32.f16.f16.f32 "
        "{%0,%1,%2,%3}, {%4,%5,%6,%7}, {%8,%9}, {%0,%1,%2,%3};\n"
        : "+f"(d.x), "+f"(d.y), "+f"(d.z), "+f"(d.w)
        : "r"(a[0]), "r"(a[1]), "r"(a[2]), "r"(a[3]), "r"(b[0]), "r"(b[1]));
}

#define CPA16(dst, src) \
    asm volatile("cp.async.cg.shared.global [%0], [%1], 16;" :: "r"(dst), "l"(src))
#define CPA16Z(dst, src, sz) \
    asm volatile("cp.async.cg.shared.global [%0], [%1], 16, %2;" :: "r"(dst), "l"(src), "r"(sz))
#define CPA_COMMIT() asm volatile("cp.async.commit_group;")
#define CPA_WAIT0()  asm volatile("cp.async.wait_group 0;")

// ---- tf32 fragment-major A tile: 128 rows x 32 k = 4096 u32 ----
__device__ __forceinline__ int a_elem_off(int mloc, int kloc) {
    int mgrp = mloc >> 4, g = mloc & 7, r8 = (mloc >> 3) & 1;
    int ks = kloc >> 3, tg = kloc & 3, khalf = (kloc >> 2) & 1;
    return (((ks * 8 + mgrp) * 32) + (g * 4 + tg)) * 4 + (khalf * 2 + r8);
}
// ---- fp16 fragment-major A tile: 128 rows x 64 k-halves = 4096 u32 ----
__device__ __forceinline__ int a_u32_off_h(int mloc, int kloc) {  // kloc even
    int mgrp = mloc >> 4, g = mloc & 7, r8 = (mloc >> 3) & 1;
    int ks = kloc >> 4, tg = (kloc >> 1) & 3, khalf = (kloc >> 3) & 1;
    return (((ks * 8 + mgrp) * 32) + (g * 4 + tg)) * 4 + (khalf * 2 + r8);
}

// ================= conversions =================
__global__ void __launch_bounds__(256) conv_plain(const float* __restrict__ in,
                                                  uint32_t* __restrict__ out, size_t n4)
{
    size_t i = (size_t)blockIdx.x * 256 + threadIdx.x;
    size_t stride = (size_t)gridDim.x * 256;
    for (; i < n4; i += stride) {
        float4 v = ((const float4*)in)[i];
        ((uint4*)out)[i] = make_uint4(f2tf(v.x), f2tf(v.y), f2tf(v.z), f2tf(v.w));
    }
}

// row-major [M,K] fp32 -> tiled-fragment tf32 ; grid (K/32, M/128)
__global__ void __launch_bounds__(256) conv_tiled(const float* __restrict__ in,
                                                  uint32_t* __restrict__ out, int K)
{
    int kt = blockIdx.x, mt = blockIdx.y;
    int nkt = K >> 5;
    size_t tb = ((size_t)mt * nkt + kt) * 4096;
    int tid = threadIdx.x;
#pragma unroll
    for (int j = 0; j < 4; j++) {
        int c = tid + j * 256;
        int mloc = c >> 3, kc = c & 7;
        float4 v = *(const float4*)(in + (size_t)(mt * 128 + mloc) * K + kt * 32 + kc * 4);
        out[tb + a_elem_off(mloc, kc * 4 + 0)] = f2tf(v.x);
        out[tb + a_elem_off(mloc, kc * 4 + 1)] = f2tf(v.y);
        out[tb + a_elem_off(mloc, kc * 4 + 2)] = f2tf(v.z);
        out[tb + a_elem_off(mloc, kc * 4 + 3)] = f2tf(v.w);
    }
}

// W [K][N] fp32 -> transposed fp16 pairs [N][K/2] u32
__global__ void __launch_bounds__(256) conv_wT(const float* __restrict__ in,
                                               uint32_t* __restrict__ out, int K, int N)
{
    __shared__ float S[64][65];
    const float* ip = in + (size_t)blockIdx.z * K * N;
    uint32_t* op = out + (size_t)blockIdx.z * ((size_t)K * N / 2);
    int n0 = blockIdx.x * 64, k0 = blockIdx.y * 64;
    int tid = threadIdx.x;
#pragma unroll
    for (int j = 0; j < 4; j++) {
        int c = tid + j * 256;
        int kr = c >> 4, nc = (c & 15) * 4;
        float4 v = *(const float4*)(ip + (size_t)(k0 + kr) * N + n0 + nc);
        S[kr][nc] = v.x; S[kr][nc+1] = v.y; S[kr][nc+2] = v.z; S[kr][nc+3] = v.w;
    }
    __syncthreads();
    int K2 = K >> 1;
#pragma unroll
    for (int j = 0; j < 8; j++) {
        int c = tid + j * 256;
        int n = c >> 5, i = c & 31;
        op[(size_t)(n0 + n) * K2 + (k0 >> 1) + i] = f2h2(S[2*i][n], S[2*i+1][n]);
    }
}

// ======== tf32 GEMM (pre-routing, R11-proven): A tiled-frag, B row-major tf32 ========
#define BSP 136
__global__ void __launch_bounds__(256, 2) gemm_tcA(
    const uint32_t* __restrict__ At, const uint32_t* __restrict__ Bt,
    const float* __restrict__ bias, float* __restrict__ C,
    int N, int Kd, int nkt)
{
    extern __shared__ uint32_t sm[];
    uint32_t* As = sm;                   // [2][4096]
    uint32_t* Bs = sm + 8192;            // [2][32*BSP]

    int m0 = blockIdx.y * 128;
    int n0 = blockIdx.x * 128;

    int tid = threadIdx.x;
    int wid = tid >> 5, lane = tid & 31;
    int wrow = wid >> 2, wn = (wid & 3) * 32;
    int g = lane >> 2, tg = lane & 3;
    int aidx = g * 4 + tg;

    uint32_t sA = (uint32_t)__cvta_generic_to_shared(As);
    uint32_t sB = (uint32_t)__cvta_generic_to_shared(Bs);

    float4 acc[4][4];
#pragma unroll
    for (int i = 0; i < 4; i++)
#pragma unroll
        for (int j = 0; j < 4; j++) acc[i][j] = make_float4(0.f, 0.f, 0.f, 0.f);

    int nk = Kd >> 5;
    size_t abase = (size_t)blockIdx.y * nkt * 4096;

    {
        const uint32_t* at = At + abase;
#pragma unroll
        for (int j = 0; j < 4; j++) {
            int c = tid + j * 256;
            CPA16(sA + c * 16, at + c * 4);
        }
#pragma unroll
        for (int j = 0; j < 4; j++) {
            int c = tid + j * 256;
            int row = c >> 5, nc = c & 31;
            CPA16(sB + (row * BSP + nc * 4) * 4, Bt + (size_t)row * N + n0 + nc * 4);
        }
        CPA_COMMIT();
    }

    for (int i = 0; i < nk; i++) {
        int buf = i & 1;
        CPA_WAIT0();
        __syncthreads();
        if (i + 1 < nk) {
            int nb = buf ^ 1;
            const uint32_t* at = At + abase + (size_t)(i + 1) * 4096;
            int k0 = (i + 1) << 5;
#pragma unroll
            for (int j = 0; j < 4; j++) {
                int c = tid + j * 256;
                CPA16(sA + (nb * 4096 + c * 4) * 4, at + c * 4);
            }
#pragma unroll
            for (int j = 0; j < 4; j++) {
                int c = tid + j * 256;
                int row = c >> 5, nc = c & 31;
                CPA16(sB + ((nb * 32 + row) * BSP + nc * 4) * 4,
                      Bt + (size_t)(k0 + row) * N + n0 + nc * 4);
            }
            CPA_COMMIT();
        }

        const uint4* Ab = (const uint4*)(As + buf * 4096);
        const uint32_t* Bb = Bs + buf * 32 * BSP;
#pragma unroll
        for (int ks = 0; ks < 4; ks++) {
            uint4 af4[4];
#pragma unroll
            for (int i2 = 0; i2 < 4; i2++)
                af4[i2] = Ab[(ks * 8 + wrow * 4 + i2) * 32 + aidx];
            uint32_t bfr[4][2];
#pragma unroll
            for (int j = 0; j < 4; j++) {
                bfr[j][0] = Bb[(ks * 8 + tg) * BSP + wn + j * 8 + g];
                bfr[j][1] = Bb[(ks * 8 + 4 + tg) * BSP + wn + j * 8 + g];
            }
#pragma unroll
            for (int i2 = 0; i2 < 4; i2++)
#pragma unroll
                for (int j = 0; j < 4; j++)
                    mma8(acc[i2][j], (const uint32_t*)&af4[i2], bfr[j]);
        }
        __syncthreads();
    }

#pragma unroll
    for (int i = 0; i < 4; i++) {
#pragma unroll
        for (int half = 0; half < 2; half++) {
            int m = m0 + wrow * 64 + i * 16 + g + half * 8;
            float* cp = C + (size_t)m * N;
#pragma unroll
            for (int j = 0; j < 4; j++) {
                int c = n0 + wn + j * 8 + tg * 2;
                float2 bp = *(const float2*)(bias + c);
                float u0 = (half ? acc[i][j].z : acc[i][j].x) + bp.x;
                float u1 = (half ? acc[i][j].w : acc[i][j].y) + bp.y;
                *(float2*)(cp + c) = make_float2(u0, u1);
            }
        }
    }
}

// ======== fp16 GEMM (expert W2): A fragment-tiled fp16, B transposed [N][K/2] ========
// C[rowidx[m]] += roww[m]*(acc+bias)
#define BSPH 36
__global__ void __launch_bounds__(256, 2) gemm_h2(
    const uint32_t* __restrict__ At, const uint32_t* __restrict__ BT,
    const float* __restrict__ bias, float* __restrict__ C,
    int N, int Kd,
    const int* __restrict__ rowidx, const float* __restrict__ roww,
    const int* __restrict__ Mcnt)
{
    extern __shared__ uint32_t sm[];
    uint32_t* As = sm;                   // [2][4096]
    uint32_t* Bs = sm + 8192;            // [2][128*BSPH]

    int Meff = *Mcnt;
    int m0 = blockIdx.y * 128;
    if (m0 >= Meff) return;
    int n0 = blockIdx.x * 128;

    int tid = threadIdx.x;
    int wid = tid >> 5, lane = tid & 31;
    int wrow = wid >> 2, wn = (wid & 3) * 32;
    int g = lane >> 2, tg = lane & 3;
    int K2 = Kd >> 1;

    uint32_t sA = (uint32_t)__cvta_generic_to_shared(As);
    uint32_t sB = (uint32_t)__cvta_generic_to_shared(Bs);

    float4 acc[4][4];
#pragma unroll
    for (int i = 0; i < 4; i++)
#pragma unroll
        for (int j = 0; j < 4; j++) acc[i][j] = make_float4(0.f, 0.f, 0.f, 0.f);

    int nk = Kd >> 6;
    size_t abase = (size_t)blockIdx.y * nk * 4096;

    {
        const uint32_t* at = At + abase;
#pragma unroll
        for (int j = 0; j < 4; j++) {
            int c = tid + j * 256;
            CPA16(sA + c * 16, at + c * 4);
        }
#pragma unroll
        for (int j = 0; j < 4; j++) {
            int c = tid + j * 256;
            int row = c >> 3, ch = c & 7;
            CPA16(sB + (row * BSPH + ch * 4) * 4, BT + (size_t)(n0 + row) * K2 + ch * 4);
        }
        CPA_COMMIT();
    }

    for (int i = 0; i < nk; i++) {
        int buf = i & 1;
        CPA_WAIT0();
        __syncthreads();
        if (i + 1 < nk) {
            int nb = buf ^ 1;
            const uint32_t* at = At + abase + (size_t)(i + 1) * 4096;
#pragma unroll
            for (int j = 0; j < 4; j++) {
                int c = tid + j * 256;
                CPA16(sA + (nb * 4096 + c * 4) * 4, at + c * 4);
            }
#pragma unroll
            for (int j = 0; j < 4; j++) {
                int c = tid + j * 256;
                int row = c >> 3, ch = c & 7;
                CPA16(sB + ((nb * 128 + row) * BSPH + ch * 4) * 4,
                      BT + (size_t)(n0 + row) * K2 + (i + 1) * 32 + ch * 4);
            }
            CPA_COMMIT();
        }

        const uint4* Ab = (const uint4*)(As + buf * 4096);
        const uint32_t* Bb = Bs + buf * 128 * BSPH;
#pragma unroll
        for (int ks = 0; ks < 4; ks++) {
            uint4 af[4];
#pragma unroll
            for (int i2 = 0; i2 < 4; i2++)
                af[i2] = Ab[(ks * 8 + wrow * 4 + i2) * 32 + lane];
            uint32_t bfr[4][2];
#pragma unroll
            for (int j = 0; j < 4; j++) {
                int n = wn + j * 8 + g;
                bfr[j][0] = Bb[n * BSPH + ks * 8 + tg];
                bfr[j][1] = Bb[n * BSPH + ks * 8 + 4 + tg];
            }
#pragma unroll
            for (int i2 = 0; i2 < 4; i2++)
#pragma unroll
                for (int j = 0; j < 4; j++)
                    mma16(acc[i2][j], (const uint32_t*)&af[i2], bfr[j]);
        }
        __syncthreads();
    }

#pragma unroll
    for (int i = 0; i < 4; i++) {
#pragma unroll
        for (int half = 0; half < 2; half++) {
            int m = m0 + wrow * 64 + i * 16 + g + half * 8;
            if (m >= Meff) continue;
            int crow = rowidx[m];
            float w = roww[m];
            float* cp = C + (size_t)crow * N;
#pragma unroll
            for (int j = 0; j < 4; j++) {
                int c = n0 + wn + j * 8 + tg * 2;
                float2 bp = *(const float2*)(bias + c);
                float u0 = (half ? acc[i][j].z : acc[i][j].x) + bp.x;
                float u1 = (half ? acc[i][j].w : acc[i][j].y) + bp.y;
                float2 old = *(float2*)(cp + c);
                old.x += w * u0; old.y += w * u1;
                *(float2*)(cp + c) = old;
            }
        }
    }
}

// ======== gathered fp16 GEMM (expert W1): A row-major pairs gathered, gelu -> tiled Ht ========
#define ASPH 36
__global__ void __launch_bounds__(256, 2) gemm_gather_h(
    const uint32_t* __restrict__ Ah, const uint32_t* __restrict__ BT,
    const float* __restrict__ bias, uint32_t* __restrict__ Ht,
    int N, int Kd,
    const int* __restrict__ rowidx, const int* __restrict__ Mcnt)
{
    extern __shared__ uint32_t sm[];
    uint32_t* As = sm;                    // [2][128*ASPH]
    uint32_t* Bs = sm + 2 * 128 * ASPH;   // [2][128*BSPH]

    int Meff = *Mcnt;
    int m0 = blockIdx.y * 128;
    if (m0 >= Meff) return;
    int n0 = blockIdx.x * 128;

    int tid = threadIdx.x;
    int wid = tid >> 5, lane = tid & 31;
    int wrow = wid >> 2, wn = (wid & 3) * 32;
    int g = lane >> 2, tg = lane & 3;
    int wm = wrow * 64;
    int K2 = Kd >> 1;

    uint32_t sA = (uint32_t)__cvta_generic_to_shared(As);
    uint32_t sB = (uint32_t)__cvta_generic_to_shared(Bs);

    int amr = tid >> 3, ack = tid & 7;
    int ga[4]; uint32_t asz[4];
#pragma unroll
    for (int j = 0; j < 4; j++) {
        int m = m0 + amr + j * 32;
        bool ok = m < Meff;
        ga[j] = ok ? rowidx[m] : 0;
        asz[j] = ok ? 16u : 0u;
    }

    float4 acc[4][4];
#pragma unroll
    for (int i = 0; i < 4; i++)
#pragma unroll
        for (int j = 0; j < 4; j++) acc[i][j] = make_float4(0.f, 0.f, 0.f, 0.f);

    int nk = Kd >> 6;

    {
#pragma unroll
        for (int j = 0; j < 4; j++) {
            int m = amr + j * 32;
            CPA16Z(sA + (m * ASPH + ack * 4) * 4, Ah + (size_t)ga[j] * K2 + ack * 4, asz[j]);
        }
#pragma unroll
        for (int j = 0; j < 4; j++) {
            int c = tid + j * 256;
            int row = c >> 3, ch = c & 7;
            CPA16(sB + (row * BSPH + ch * 4) * 4, BT + (size_t)(n0 + row) * K2 + ch * 4);
        }
        CPA_COMMIT();
    }

    for (int i = 0; i < nk; i++) {
        int buf = i & 1;
        CPA_WAIT0();
        __syncthreads();
        if (i + 1 < nk) {
            int nb = buf ^ 1;
#pragma unroll
            for (int j = 0; j < 4; j++) {
                int m = amr + j * 32;
                CPA16Z(sA + ((nb * 128 + m) * ASPH + ack * 4) * 4,
                       Ah + (size_t)ga[j] * K2 + (i + 1) * 32 + ack * 4, asz[j]);
            }
#pragma unroll
            for (int j = 0; j < 4; j++) {
                int c = tid + j * 256;
                int row = c >> 3, ch = c & 7;
                CPA16(sB + ((nb * 128 + row) * BSPH + ch * 4) * 4,
                      BT + (size_t)(n0 + row) * K2 + (i + 1) * 32 + ch * 4);
            }
            CPA_COMMIT();
        }

        const uint32_t* Ab = As + buf * 128 * ASPH;
        const uint32_t* Bb = Bs + buf * 128 * BSPH;
#pragma unroll
        for (int ks = 0; ks < 4; ks++) {
            uint32_t af[4][4];
#pragma unroll
            for (int i2 = 0; i2 < 4; i2++) {
                int r0 = wm + i2 * 16 + g, r1 = r0 + 8;
                af[i2][0] = Ab[r0 * ASPH + ks * 8 + tg];
                af[i2][1] = Ab[r1 * ASPH + ks * 8 + tg];
                af[i2][2] = Ab[r0 * ASPH + ks * 8 + 4 + tg];
                af[i2][3] = Ab[r1 * ASPH + ks * 8 + 4 + tg];
            }
            uint32_t bfr[4][2];
#pragma unroll
            for (int j = 0; j < 4; j++) {
                int n = wn + j * 8 + g;
                bfr[j][0] = Bb[n * BSPH + ks * 8 + tg];
                bfr[j][1] = Bb[n * BSPH + ks * 8 + 4 + tg];
            }
#pragma unroll
            for (int i2 = 0; i2 < 4; i2++)
#pragma unroll
                for (int j = 0; j < 4; j++)
                    mma16(acc[i2][j], af[i2], bfr[j]);
        }
        __syncthreads();
    }

    int nktH = N >> 6;
#pragma unroll
    for (int i = 0; i < 4; i++) {
#pragma unroll
        for (int half = 0; half < 2; half++) {
            int m = m0 + wm + i * 16 + g + half * 8;
            if (m >= Meff) continue;
            size_t rowtb = (size_t)(m >> 7) * nktH;
            int mloc = m & 127;
#pragma unroll
            for (int j = 0; j < 4; j++) {
                int c = n0 + wn + j * 8 + tg * 2;
                float2 bp = *(const float2*)(bias + c);
                float u0 = gelu_f((half ? acc[i][j].z : acc[i][j].x) + bp.x);
                float u1 = gelu_f((half ? acc[i][j].w : acc[i][j].y) + bp.y);
                size_t tb = (rowtb + (c >> 6)) * 4096;
                Ht[tb + a_u32_off_h(mloc, c & 63)] = f2h2(u0, u1);
            }
        }
    }
}

// ---------------- flash attention, tf32 (R11-proven), epilogue -> tiled tf32 AO ----------------
#define KP 68
#define VP 72
__global__ void __launch_bounds__(128) attn_tc(
    const float* __restrict__ Q, const float* __restrict__ Kin,
    const float* __restrict__ Vin, uint32_t* __restrict__ AOt)
{
    extern __shared__ uint32_t smx[];
    uint32_t* Ks = smx;
    uint32_t* Ps = smx + 64 * KP;
    uint32_t* Vs = smx + 2 * 64 * KP;

    int bh = blockIdx.y;
    int b = bh >> 4, h = bh & 15;
    int q0 = blockIdx.x * 64;
    int tid = threadIdx.x;
    int wid = tid >> 5, lane = tid & 31;
    int g = lane >> 2, tg = lane & 3;
    int w16 = wid * 16;
    size_t base = (size_t)(b * Sc) * Dc + h * 64;
    const unsigned fullm = 0xffffffffu;

#pragma unroll
    for (int j = 0; j < 8; j++) {
        int idx = tid + j * 128;
        int r = idx >> 4, c = (idx & 15) * 4;
        float4 q4 = *(const float4*)(Q + base + (size_t)(q0 + r) * Dc + c);
        *(uint4*)&Ks[r * KP + c] = make_uint4(f2tf(q4.x), f2tf(q4.y), f2tf(q4.z), f2tf(q4.w));
    }
    __syncthreads();
    uint32_t qf[8][4];
#pragma unroll
    for (int d0 = 0; d0 < 8; d0++) {
        qf[d0][0] = Ks[(w16 + g) * KP + d0 * 8 + tg];
        qf[d0][1] = Ks[(w16 + 8 + g) * KP + d0 * 8 + tg];
        qf[d0][2] = Ks[(w16 + g) * KP + d0 * 8 + 4 + tg];
        qf[d0][3] = Ks[(w16 + 8 + g) * KP + d0 * 8 + 4 + tg];
    }

    float m0r = -1e30f, m1r = -1e30f;
    float l0r = 0.f, l1r = 0.f;
    float4 of[8];
#pragma unroll
    for (int j = 0; j < 8; j++) of[j] = make_float4(0.f, 0.f, 0.f, 0.f);

    for (int kv0 = 0; kv0 < Sc; kv0 += 64) {
        __syncthreads();
#pragma unroll
        for (int j = 0; j < 8; j++) {
            int idx = tid + j * 128;
            int r = idx >> 4, c = (idx & 15) * 4;
            float4 k4 = *(const float4*)(Kin + base + (size_t)(kv0 + r) * Dc + c);
            float4 v4 = *(const float4*)(Vin + base + (size_t)(kv0 + r) * Dc + c);
            *(uint4*)&Ks[r * KP + c] = make_uint4(f2tf(k4.x), f2tf(k4.y), f2tf(k4.z), f2tf(k4.w));
            *(uint4*)&Vs[r * VP + c] = make_uint4(f2tf(v4.x), f2tf(v4.y), f2tf(v4.z), f2tf(v4.w));
        }
        __syncthreads();

        float4 sa[8];
#pragma unroll
        for (int j = 0; j < 8; j++) sa[j] = make_float4(0.f, 0.f, 0.f, 0.f);
#pragma unroll
        for (int d0 = 0; d0 < 8; d0++) {
#pragma unroll
            for (int j = 0; j < 8; j++) {
                uint32_t bf[2];
                bf[0] = Ks[(j * 8 + g) * KP + d0 * 8 + tg];
                bf[1] = Ks[(j * 8 + g) * KP + d0 * 8 + 4 + tg];
                mma8(sa[j], qf[d0], bf);
            }
        }

        float t0 = -1e30f, t1 = -1e30f;
#pragma unroll
        for (int j = 0; j < 8; j++) {
            sa[j].x *= 0.125f; sa[j].y *= 0.125f; sa[j].z *= 0.125f; sa[j].w *= 0.125f;
            t0 = fmaxf(t0, fmaxf(sa[j].x, sa[j].y));
            t1 = fmaxf(t1, fmaxf(sa[j].z, sa[j].w));
        }
        t0 = fmaxf(t0, __shfl_xor_sync(fullm, t0, 1));
        t0 = fmaxf(t0, __shfl_xor_sync(fullm, t0, 2));
        t1 = fmaxf(t1, __shfl_xor_sync(fullm, t1, 1));
        t1 = fmaxf(t1, __shfl_xor_sync(fullm, t1, 2));
        float mn0 = fmaxf(m0r, t0), mn1 = fmaxf(m1r, t1);
        float al0 = __expf(m0r - mn0), al1 = __expf(m1r - mn1);
        float rs0 = 0.f, rs1 = 0.f;
#pragma unroll
        for (int j = 0; j < 8; j++) {
            sa[j].x = __expf(sa[j].x - mn0); sa[j].y = __expf(sa[j].y - mn0);
            sa[j].z = __expf(sa[j].z - mn1); sa[j].w = __expf(sa[j].w - mn1);
            rs0 += sa[j].x + sa[j].y; rs1 += sa[j].z + sa[j].w;
        }
        rs0 += __shfl_xor_sync(fullm, rs0, 1); rs0 += __shfl_xor_sync(fullm, rs0, 2);
        rs1 += __shfl_xor_sync(fullm, rs1, 1); rs1 += __shfl_xor_sync(fullm, rs1, 2);
        l0r = l0r * al0 + rs0; l1r = l1r * al1 + rs1;
        m0r = mn0; m1r = mn1;
#pragma unroll
        for (int j = 0; j < 8; j++) {
            of[j].x *= al0; of[j].y *= al0; of[j].z *= al1; of[j].w *= al1;
        }

#pragma unroll
        for (int j = 0; j < 8; j++) {
            int col = j * 8 + tg * 2;
            Ps[(w16 + g) * KP + col]     = f2tf(sa[j].x);
            Ps[(w16 + g) * KP + col + 1] = f2tf(sa[j].y);
            Ps[(w16 + 8 + g) * KP + col]     = f2tf(sa[j].z);
            Ps[(w16 + 8 + g) * KP + col + 1] = f2tf(sa[j].w);
        }
        __syncwarp();

#pragma unroll
        for (int k0 = 0; k0 < 8; k0++) {
            uint32_t af[4];
            af[0] = Ps[(w16 + g) * KP + k0 * 8 + tg];
            af[1] = Ps[(w16 + 8 + g) * KP + k0 * 8 + tg];
            af[2] = Ps[(w16 + g) * KP + k0 * 8 + 4 + tg];
            af[3] = Ps[(w16 + 8 + g) * KP + k0 * 8 + 4 + tg];
#pragma unroll
            for (int j = 0; j < 8; j++) {
                uint32_t bf[2];
                bf[0] = Vs[(k0 * 8 + tg) * VP + j * 8 + g];
                bf[1] = Vs[(k0 * 8 + 4 + tg) * VP + j * 8 + g];
                mma8(of[j], af, bf);
            }
        }
    }

    float inv0 = 1.f / l0r, inv1 = 1.f / l1r;
    int mg0 = b * Sc + q0 + w16 + g;
    int mg1 = mg0 + 8;
    size_t rtb0 = (size_t)(mg0 >> 7) * 32;
    size_t rtb1 = (size_t)(mg1 >> 7) * 32;
    int ml0 = mg0 & 127, ml1 = mg1 & 127;
#pragma unroll
    for (int j = 0; j < 8; j++) {
        int col = h * 64 + j * 8 + tg * 2;
        size_t tb0 = (rtb0 + (col >> 5)) * 4096;
        size_t tb1 = (rtb1 + (col >> 5)) * 4096;
        AOt[tb0 + a_elem_off(ml0, col & 31)]       = f2tf(of[j].x * inv0);
        AOt[tb0 + a_elem_off(ml0, (col + 1) & 31)] = f2tf(of[j].y * inv0);
        AOt[tb1 + a_elem_off(ml1, col & 31)]       = f2tf(of[j].z * inv1);
        AOt[tb1 + a_elem_off(ml1, (col + 1) & 31)] = f2tf(of[j].w * inv1);
    }
}

// ---------------- residual + layernorm (optional fp16-pair copy) ----------------
__global__ void __launch_bounds__(256) add_ln_kernel(
    const float* __restrict__ xin, const float* __restrict__ res,
    const float* __restrict__ g, const float* __restrict__ bta,
    float* __restrict__ out, uint32_t* __restrict__ outh)
{
    int t = blockIdx.x;
    int tid = threadIdx.x;
    const float4 xv = ((const float4*)(xin + (size_t)t * Dc))[tid];
    const float4 rv = ((const float4*)(res + (size_t)t * Dc))[tid];
    float v[4] = {xv.x + rv.x, xv.y + rv.y, xv.z + rv.z, xv.w + rv.w};
    float s  = v[0] + v[1] + v[2] + v[3];
    float sq = v[0]*v[0] + v[1]*v[1] + v[2]*v[2] + v[3]*v[3];
#pragma unroll
    for (int off = 16; off; off >>= 1) {
        s  += __shfl_xor_sync(0xffffffffu, s, off);
        sq += __shfl_xor_sync(0xffffffffu, sq, off);
    }
    __shared__ float ss[8], qq[8];
    __shared__ float smu, srstd;
    int wid = tid >> 5;
    if ((tid & 31) == 0) { ss[wid] = s; qq[wid] = sq; }
    __syncthreads();
    if (tid == 0) {
        float ts = 0.f, tq = 0.f;
#pragma unroll
        for (int i = 0; i < 8; i++) { ts += ss[i]; tq += qq[i]; }
        float mu = ts / (float)Dc;
        float var = tq / (float)Dc - mu * mu;
        smu = mu; srstd = rsqrtf(var + 1e-5f);
    }
    __syncthreads();
    float mu = smu, rstd = srstd;
    float4 g4 = ((const float4*)g)[tid];
    float4 b4 = ((const float4*)bta)[tid];
    float4 o4;
    o4.x = (v[0]-mu)*rstd*g4.x + b4.x;
    o4.y = (v[1]-mu)*rstd*g4.y + b4.y;
    o4.z = (v[2]-mu)*rstd*g4.z + b4.z;
    o4.w = (v[3]-mu)*rstd*g4.w + b4.w;
    ((float4*)(out + (size_t)t * Dc))[tid] = o4;
    if (outh)
        ((uint2*)(outh + (size_t)t * (Dc / 2)))[tid] =
            make_uint2(f2h2(o4.x, o4.y), f2h2(o4.z, o4.w));
}

// ---------------- gate ----------------
__global__ void __launch_bounds__(256) gate_kernel(
    const float* __restrict__ x1, const float* __restrict__ gW,
    const float* __restrict__ gb)
{
    int t = blockIdx.x;
    int tid = threadIdx.x;
    float part[Ec];
#pragma unroll
    for (int e = 0; e < Ec; e++) part[e] = 0.f;
    const float* xr = x1 + (size_t)t * Dc;
    for (int d = tid; d < Dc; d += 256) {
        float xv = xr[d];
        const float* wr = gW + d * Ec;
#pragma unroll
        for (int e = 0; e < Ec; e++) part[e] += xv * wr[e];
    }
    __shared__ float sm[Ec][264];
#pragma unroll
    for (int e = 0; e < Ec; e++) sm[e][tid] = part[e];
    __syncthreads();
    for (int off = 128; off; off >>= 1) {
        if (tid < off) {
#pragma unroll
            for (int e = 0; e < Ec; e++) sm[e][tid] += sm[e][tid + off];
        }
        __syncthreads();
    }
    if (tid == 0) {
        float lg[Ec], sc[Ec];
        float m = -1e30f;
#pragma unroll
        for (int e = 0; e < Ec; e++) { lg[e] = sm[e][0] + gb[e]; m = fmaxf(m, lg[e]); }
        float sum = 0.f;
#pragma unroll
        for (int e = 0; e < Ec; e++) { sc[e] = expf(lg[e] - m); sum += sc[e]; }
        float inv = 1.f / sum;
#pragma unroll
        for (int e = 0; e < Ec; e++) { sc[e] *= inv; g_scores[t * Ec + e] = sc[e]; }
        int a1 = 0;
#pragma unroll
        for (int e = 1; e < Ec; e++) if (sc[e] > sc[a1]) a1 = e;
        int a2 = (a1 == 0) ? 1 : 0;
#pragma unroll
        for (int e = 0; e < Ec; e++) if (e != a1 && sc[e] > sc[a2]) a2 = e;
        float ws = sc[a1] + sc[a2];
        float w1 = sc[a1] / ws, w2 = sc[a2] / ws;
        int p1 = atomicAdd(&g_cnt[a1], 1);
        g_eidx[a1 * Tc + p1] = t; g_ewgt[a1 * Tc + p1] = w1;
        int p2 = atomicAdd(&g_cnt[a2], 1);
        g_eidx[a2 * Tc + p2] = t; g_ewgt[a2 * Tc + p2] = w2;
    }
}

// ---------------- aux loss ----------------
__global__ void __launch_bounds__(256) aux_kernel(float* __restrict__ out)
{
    int tid = threadIdx.x;
    float part[Ec];
#pragma unroll
    for (int e = 0; e < Ec; e++) part[e] = 0.f;
    for (int t = tid; t < Tc; t += 256) {
#pragma unroll
        for (int e = 0; e < Ec; e++) part[e] += g_scores[t * Ec + e];
    }
    __shared__ float sm[Ec][264];
#pragma unroll
    for (int e = 0; e < Ec; e++) sm[e][tid] = part[e];
    __syncthreads();
    for (int off = 128; off; off >>= 1) {
        if (tid < off) {
#pragma unroll
            for (int e = 0; e < Ec; e++) sm[e][tid] += sm[e][tid + off];
        }
        __syncthreads();
    }
    if (tid == 0) {
        float aux = 0.f;
#pragma unroll
        for (int e = 0; e < Ec; e++) {
            float ef = (float)g_cnt[e] / (float)(Tc * Kc);
            float rw = sm[e][0] / (float)Tc;
            aux += ef * rw;
        }
        out[0] = aux * (float)Ec;
    }
}

// ---------------- state reset ----------------
__global__ void zero_cnt_kernel() {
    if (threadIdx.x < Ec) g_cnt[threadIdx.x] = 0;
}
__global__ void zero_moe_kernel() {
    size_t i = ((size_t)blockIdx.x * 256 + threadIdx.x) * 4;
    *(float4*)(g_moe + i) = make_float4(0.f, 0.f, 0.f, 0.f);
}

// ---------------- launch ----------------
extern "C" void kernel_launch(void* const* d_in, const int* in_sizes, int n_in,
                              void* d_out, int out_size)
{
    (void)in_sizes; (void)n_in; (void)out_size;
    const float* x     = (const float*)d_in[0];
    const float* Wq    = (const float*)d_in[1];
    const float* bq    = (const float*)d_in[2];
    const float* Wk    = (const float*)d_in[3];
    const float* bk    = (const float*)d_in[4];
    const float* Wv    = (const float*)d_in[5];
    const float* bv    = (const float*)d_in[6];
    const float* Wo    = (const float*)d_in[7];
    const float* bo    = (const float*)d_in[8];
    const float* g1    = (const float*)d_in[9];
    const float* beta1 = (const float*)d_in[10];
    const float* gateW = (const float*)d_in[11];
    const float* gateb = (const float*)d_in[12];
    const float* eW1   = (const float*)d_in[13];
    const float* eb1   = (const float*)d_in[14];
    const float* eW2   = (const float*)d_in[15];
    const float* eb2   = (const float*)d_in[16];
    const float* g2    = (const float*)d_in[17];
    const float* beta2 = (const float*)d_in[18];
    float* out = (float*)d_out;

    float *pQ, *pK, *pV, *pP, *pX1, *pMoe, *pWgt;
    uint32_t *pxt, *pWt, *pAOt, *pX1h, *pHt, *peW1T, *peW2T;
    int *pCnt, *pIdx;
    cudaGetSymbolAddress((void**)&pxt,   g_xt);
    cudaGetSymbolAddress((void**)&pWt,   g_Wt);
    cudaGetSymbolAddress((void**)&pQ,    g_Q);
    cudaGetSymbolAddress((void**)&pK,    g_Kb);
    cudaGetSymbolAddress((void**)&pV,    g_Vb);
    cudaGetSymbolAddress((void**)&pAOt,  g_AOt);
    cudaGetSymbolAddress((void**)&pP,    g_P);
    cudaGetSymbolAddress((void**)&pX1,   g_X1);
    cudaGetSymbolAddress((void**)&pX1h,  g_X1h);
    cudaGetSymbolAddress((void**)&pMoe,  g_moe);
    cudaGetSymbolAddress((void**)&pHt,   g_Ht);
    cudaGetSymbolAddress((void**)&peW1T, g_eW1T);
    cudaGetSymbolAddress((void**)&peW2T, g_eW2T);
    cudaGetSymbolAddress((void**)&pCnt,  g_cnt);
    cudaGetSymbolAddress((void**)&pIdx,  g_eidx);
    cudaGetSymbolAddress((void**)&pWgt,  g_ewgt);

    const int attn_smem = (2 * 64 * KP + 64 * VP) * 4;            // 53248
    const int gA_smem   = (2 * 4096 + 2 * 32 * BSP) * 4;          // 67584
    const int gH_smem   = (2 * 4096 + 2 * 128 * BSPH) * 4;        // 69632
    const int gG_smem   = (2 * 128 * ASPH + 2 * 128 * BSPH) * 4;  // 73728
    cudaFuncSetAttribute(attn_tc, cudaFuncAttributeMaxDynamicSharedMemorySize, attn_smem);
    cudaFuncSetAttribute(gemm_tcA, cudaFuncAttributeMaxDynamicSharedMemorySize, gA_smem);
    cudaFuncSetAttribute(gemm_h2, cudaFuncAttributeMaxDynamicSharedMemorySize, gH_smem);
    cudaFuncSetAttribute(gemm_gather_h, cudaFuncAttributeMaxDynamicSharedMemorySize, gG_smem);

    zero_cnt_kernel<<<1, 32>>>();
    zero_moe_kernel<<<(Tc * Dc) / 1024, 256>>>();

    // conversions: tf32 for pre-routing, fp16 for experts
    conv_tiled<<<dim3(Dc / 32, Tc / 128), 256>>>(x, pxt, Dc);
    conv_plain<<<512, 256>>>(Wq, pWt + 0 * (size_t)Dc * Dc, (size_t)Dc * Dc / 4);
    conv_plain<<<512, 256>>>(Wk, pWt + 1 * (size_t)Dc * Dc, (size_t)Dc * Dc / 4);
    conv_plain<<<512, 256>>>(Wv, pWt + 2 * (size_t)Dc * Dc, (size_t)Dc * Dc / 4);
    conv_plain<<<512, 256>>>(Wo, pWt + 3 * (size_t)Dc * Dc, (size_t)Dc * Dc / 4);
    conv_wT<<<dim3(Fc / 64, Dc / 64, Ec), 256>>>(eW1, peW1T, Dc, Fc);
    conv_wT<<<dim3(Dc / 64, Fc / 64, Ec), 256>>>(eW2, peW2T, Fc, Dc);

    dim3 gD(Dc / 128, Tc / 128);   // (8, 64)
    gemm_tcA<<<gD, 256, gA_smem>>>(pxt, pWt + 0 * (size_t)Dc * Dc, bq, pQ, Dc, Dc, Dc / 32);
    gemm_tcA<<<gD, 256, gA_smem>>>(pxt, pWt + 1 * (size_t)Dc * Dc, bk, pK, Dc, Dc, Dc / 32);
    gemm_tcA<<<gD, 256, gA_smem>>>(pxt, pWt + 2 * (size_t)Dc * Dc, bv, pV, Dc, Dc, Dc / 32);

    attn_tc<<<dim3(Sc / 64, Bc * Hc), 128, attn_smem>>>(pQ, pK, pV, pAOt);

    gemm_tcA<<<gD, 256, gA_smem>>>(pAOt, pWt + 3 * (size_t)Dc * Dc, bo, pP, Dc, Dc, Dc / 32);
    add_ln_kernel<<<Tc, 256>>>(x, pP, g1, beta1, pX1, pX1h);

    gate_kernel<<<Tc, 256>>>(pX1, gateW, gateb);

    dim3 gF(Fc / 128, Tc / 128);   // (32, 64)
    for (int e = 0; e < Ec; e++) {
        gemm_gather_h<<<gF, 256, gG_smem>>>(pX1h, peW1T + (size_t)e * Dc * Fc / 2, eb1 + e * Fc,
                                            pHt, Fc, Dc, pIdx + e * Tc, pCnt + e);
        gemm_h2<<<gD, 256, gH_smem>>>(pHt, peW2T + (size_t)e * Fc * Dc / 2, eb2 + e * Dc,
                                      pMoe, Dc, Fc,
                                      pIdx + e * Tc, pWgt + e * Tc, pCnt + e);
    }

    add_ln_kernel<<<Tc, 256>>>(pX1, pMoe, g2, beta2, out, nullptr);
    aux_kernel<<<1, 256>>>(out + (size_t)Tc * Dc);
}

// round 16
// speedup vs baseline: 7.6897x; 1.0463x over previous
#include <cuda_runtime.h>
#include <cuda_fp16.h>
#include <cstdint>

#define Bc 4
#define Sc 2048
#define Dc 1024
#define Hc 16
#define HDc 64
#define Fc 4096
#define Ec 8
#define Kc 2
#define Tc (Bc*Sc)   /* 8192 */

// ---------------- scratch (static device globals; no allocation) ----------------
__device__ uint32_t g_xt[Tc*Dc];              // x, tiled tf32
__device__ uint32_t g_Wt[4][Dc*Dc];           // Wq,Wk,Wv,Wo tf32
__device__ uint32_t g_Qt[Tc*Dc];              // Q row-major tf32 bits
__device__ uint32_t g_Kf[Tc*Dc];              // K fragment-tiled per (b,h,kvtile)
__device__ uint32_t g_Vf[Tc*Dc];              // V fragment-tiled per (b,h,kvtile)
__device__ uint32_t g_AOt[Tc*Dc];             // attention out, tiled tf32
__device__ float    g_P[Tc*Dc];
__device__ float    g_X1[Tc*Dc];
__device__ uint32_t g_X1h[Tc*Dc/2];           // X1, row-major fp16 pairs (MoE gather)
__device__ float    g_moe[Tc*Dc];
__device__ uint32_t g_Ht[(size_t)Tc*Fc/2];    // expert hidden, fragment-tiled fp16
__device__ uint32_t g_eW1T[(size_t)Ec*Dc*Fc/2];   // fp16 transposed [N][K/2]
__device__ uint32_t g_eW2T[(size_t)Ec*Fc*Dc/2];
__device__ int   g_cnt[Ec];
__device__ int   g_eidx[Ec*Tc];
__device__ float g_ewgt[Ec*Tc];
__device__ float g_scores[Tc*Ec];

__device__ __forceinline__ float gelu_f(float v) {
    return 0.5f * v * (1.0f + erff(v * 0.70710678118654752f));
}
__device__ __forceinline__ uint32_t f2tf(float f) {
    uint32_t u; asm("cvt.rna.tf32.f32 %0, %1;" : "=r"(u) : "f"(f)); return u;
}
__device__ __forceinline__ uint32_t f2h2(float lo, float hi) {
    __half2 h = __floats2half2_rn(lo, hi);
    return *reinterpret_cast<uint32_t*>(&h);
}
// tf32: D += A(16x8) * B(8x8)
__device__ __forceinline__ void mma8(float4& d, const uint32_t* a, const uint32_t* b) {
    asm volatile(
        "mma.sync.aligned.m16n8k8.row.col.f32.tf32.tf32.f32 "
        "{%0,%1,%2,%3}, {%4,%5,%6,%7}, {%8,%9}, {%0,%1,%2,%3};\n"
        : "+f"(d.x), "+f"(d.y), "+f"(d.z), "+f"(d.w)
        : "r"(a[0]), "r"(a[1]), "r"(a[2]), "r"(a[3]), "r"(b[0]), "r"(b[1]));
}
// fp16: D += A(16x16) * B(16x8)
__device__ __forceinline__ void mma16(float4& d, const uint32_t* a, const uint32_t* b) {
    asm volatile(
        "mma.sync.aligned.m16n8k16.row.col.f32.f16.f16.f32 "
        "{%0,%1,%2,%3}, {%4,%5,%6,%7}, {%8,%9}, {%0,%1,%2,%3};\n"
        : "+f"(d.x), "+f"(d.y), "+f"(d.z), "+f"(d.w)
        : "r"(a[0]), "r"(a[1]), "r"(a[2]), "r"(a[3]), "r"(b[0]), "r"(b[1]));
}

#define CPA16(dst, src) \
    asm volatile("cp.async.cg.shared.global [%0], [%1], 16;" :: "r"(dst), "l"(src))
#define CPA16Z(dst, src, sz) \
    asm volatile("cp.async.cg.shared.global [%0], [%1], 16, %2;" :: "r"(dst), "l"(src), "r"(sz))
#define CPA_COMMIT() asm volatile("cp.async.commit_group;")
#define CPA_WAIT0()  asm volatile("cp.async.wait_group 0;")
#define CPA_WAIT1()  asm volatile("cp.async.wait_group 1;")

// ---- tf32 fragment-major A tile: 128 rows x 32 k = 4096 u32 ----
__device__ __forceinline__ int a_elem_off(int mloc, int kloc) {
    int mgrp = mloc >> 4, g = mloc & 7, r8 = (mloc >> 3) & 1;
    int ks = kloc >> 3, tg = kloc & 3, khalf = (kloc >> 2) & 1;
    return (((ks * 8 + mgrp) * 32) + (g * 4 + tg)) * 4 + (khalf * 2 + r8);
}
// ---- fp16 fragment-major A tile: 128 rows x 64 k-halves = 4096 u32 ----
__device__ __forceinline__ int a_u32_off_h(int mloc, int kloc) {  // kloc even
    int mgrp = mloc >> 4, g = mloc & 7, r8 = (mloc >> 3) & 1;
    int ks = kloc >> 4, tg = (kloc >> 1) & 3, khalf = (kloc >> 3) & 1;
    return (((ks * 8 + mgrp) * 32) + (g * 4 + tg)) * 4 + (khalf * 2 + r8);
}
// ---- attention K B-frag tile (64kv x 64d = 4096 u32): kv=(jj,gg), d ----
__device__ __forceinline__ int k_frag_off(int jj, int gg, int d) {
    return (((jj * 4 + (d >> 4)) * 32) + (gg * 4 + (d & 3))) * 4
         + ((((d >> 3) & 1) << 1) | ((d & 7) >> 2));
}
// ---- attention V B-frag tile (64kv x 64d = 4096 u32): kv, d=(jj,gg) ----
__device__ __forceinline__ int v_frag_off(int kv, int d) {
    return ((((d >> 3) * 4 + (kv >> 4)) * 32) + ((d & 7) * 4 + (kv & 3))) * 4
         + ((((kv >> 3) & 1) << 1) | ((kv & 7) >> 2));
}

// ================= conversions =================
__global__ void __launch_bounds__(256) conv_plain(const float* __restrict__ in,
                                                  uint32_t* __restrict__ out, size_t n4)
{
    size_t i = (size_t)blockIdx.x * 256 + threadIdx.x;
    size_t stride = (size_t)gridDim.x * 256;
    for (; i < n4; i += stride) {
        float4 v = ((const float4*)in)[i];
        ((uint4*)out)[i] = make_uint4(f2tf(v.x), f2tf(v.y), f2tf(v.z), f2tf(v.w));
    }
}

// row-major [M,K] fp32 -> tiled-fragment tf32 ; grid (K/32, M/128)
__global__ void __launch_bounds__(256) conv_tiled(const float* __restrict__ in,
                                                  uint32_t* __restrict__ out, int K)
{
    int kt = blockIdx.x, mt = blockIdx.y;
    int nkt = K >> 5;
    size_t tb = ((size_t)mt * nkt + kt) * 4096;
    int tid = threadIdx.x;
#pragma unroll
    for (int j = 0; j < 4; j++) {
        int c = tid + j * 256;
        int mloc = c >> 3, kc = c & 7;
        float4 v = *(const float4*)(in + (size_t)(mt * 128 + mloc) * K + kt * 32 + kc * 4);
        out[tb + a_elem_off(mloc, kc * 4 + 0)] = f2tf(v.x);
        out[tb + a_elem_off(mloc, kc * 4 + 1)] = f2tf(v.y);
        out[tb + a_elem_off(mloc, kc * 4 + 2)] = f2tf(v.z);
        out[tb + a_elem_off(mloc, kc * 4 + 3)] = f2tf(v.w);
    }
}

// W [K][N] fp32 -> transposed fp16 pairs [N][K/2] u32
__global__ void __launch_bounds__(256) conv_wT(const float* __restrict__ in,
                                               uint32_t* __restrict__ out, int K, int N)
{
    __shared__ float S[64][65];
    const float* ip = in + (size_t)blockIdx.z * K * N;
    uint32_t* op = out + (size_t)blockIdx.z * ((size_t)K * N / 2);
    int n0 = blockIdx.x * 64, k0 = blockIdx.y * 64;
    int tid = threadIdx.x;
#pragma unroll
    for (int j = 0; j < 4; j++) {
        int c = tid + j * 256;
        int kr = c >> 4, nc = (c & 15) * 4;
        float4 v = *(const float4*)(ip + (size_t)(k0 + kr) * N + n0 + nc);
        S[kr][nc] = v.x; S[kr][nc+1] = v.y; S[kr][nc+2] = v.z; S[kr][nc+3] = v.w;
    }
    __syncthreads();
    int K2 = K >> 1;
#pragma unroll
    for (int j = 0; j < 8; j++) {
        int c = tid + j * 256;
        int n = c >> 5, i = c & 31;
        op[(size_t)(n0 + n) * K2 + (k0 >> 1) + i] = f2h2(S[2*i][n], S[2*i+1][n]);
    }
}

// ======== tf32 GEMM (pre-routing): A tiled-frag, B row-major tf32 ========
// MODE 0: fp32 C=acc+bias ; MODE 4: Cu u32 tf32 row-major (Q)
// MODE 5: Cu = K fragment-tiled ; MODE 6: Cu = V fragment-tiled
#define BSP 136
template<int MODE>
__global__ void __launch_bounds__(256, 2) gemm_tcA(
    const uint32_t* __restrict__ At, const uint32_t* __restrict__ Bt,
    const float* __restrict__ bias, float* __restrict__ C, uint32_t* __restrict__ Cu,
    int N, int Kd, int nkt)
{
    extern __shared__ uint32_t sm[];
    uint32_t* As = sm;                   // [2][4096]
    uint32_t* Bs = sm + 8192;            // [2][32*BSP]

    int m0 = blockIdx.y * 128;
    int n0 = blockIdx.x * 128;

    int tid = threadIdx.x;
    int wid = tid >> 5, lane = tid & 31;
    int wrow = wid >> 2, wn = (wid & 3) * 32;
    int g = lane >> 2, tg = lane & 3;
    int aidx = g * 4 + tg;

    uint32_t sA = (uint32_t)__cvta_generic_to_shared(As);
    uint32_t sB = (uint32_t)__cvta_generic_to_shared(Bs);

    float4 acc[4][4];
#pragma unroll
    for (int i = 0; i < 4; i++)
#pragma unroll
        for (int j = 0; j < 4; j++) acc[i][j] = make_float4(0.f, 0.f, 0.f, 0.f);

    int nk = Kd >> 5;
    size_t abase = (size_t)blockIdx.y * nkt * 4096;

    {
        const uint32_t* at = At + abase;
#pragma unroll
        for (int j = 0; j < 4; j++) {
            int c = tid + j * 256;
            CPA16(sA + c * 16, at + c * 4);
        }
#pragma unroll
        for (int j = 0; j < 4; j++) {
            int c = tid + j * 256;
            int row = c >> 5, nc = c & 31;
            CPA16(sB + (row * BSP + nc * 4) * 4, Bt + (size_t)row * N + n0 + nc * 4);
        }
        CPA_COMMIT();
    }

    for (int i = 0; i < nk; i++) {
        int buf = i & 1;
        CPA_WAIT0();
        __syncthreads();
        if (i + 1 < nk) {
            int nb = buf ^ 1;
            const uint32_t* at = At + abase + (size_t)(i + 1) * 4096;
            int k0 = (i + 1) << 5;
#pragma unroll
            for (int j = 0; j < 4; j++) {
                int c = tid + j * 256;
                CPA16(sA + (nb * 4096 + c * 4) * 4, at + c * 4);
            }
#pragma unroll
            for (int j = 0; j < 4; j++) {
                int c = tid + j * 256;
                int row = c >> 5, nc = c & 31;
                CPA16(sB + ((nb * 32 + row) * BSP + nc * 4) * 4,
                      Bt + (size_t)(k0 + row) * N + n0 + nc * 4);
            }
            CPA_COMMIT();
        }

        const uint4* Ab = (const uint4*)(As + buf * 4096);
        const uint32_t* Bb = Bs + buf * 32 * BSP;
#pragma unroll
        for (int ks = 0; ks < 4; ks++) {
            uint4 af4[4];
#pragma unroll
            for (int i2 = 0; i2 < 4; i2++)
                af4[i2] = Ab[(ks * 8 + wrow * 4 + i2) * 32 + aidx];
            uint32_t bfr[4][2];
#pragma unroll
            for (int j = 0; j < 4; j++) {
                bfr[j][0] = Bb[(ks * 8 + tg) * BSP + wn + j * 8 + g];
                bfr[j][1] = Bb[(ks * 8 + 4 + tg) * BSP + wn + j * 8 + g];
            }
#pragma unroll
            for (int i2 = 0; i2 < 4; i2++)
#pragma unroll
                for (int j = 0; j < 4; j++)
                    mma8(acc[i2][j], (const uint32_t*)&af4[i2], bfr[j]);
        }
        __syncthreads();
    }

#pragma unroll
    for (int i = 0; i < 4; i++) {
#pragma unroll
        for (int half = 0; half < 2; half++) {
            int m = m0 + wrow * 64 + i * 16 + g + half * 8;
#pragma unroll
            for (int j = 0; j < 4; j++) {
                int c = n0 + wn + j * 8 + tg * 2;
                float2 bp = *(const float2*)(bias + c);
                float u0 = (half ? acc[i][j].z : acc[i][j].x) + bp.x;
                float u1 = (half ? acc[i][j].w : acc[i][j].y) + bp.y;
                if (MODE == 0) {
                    *(float2*)(C + (size_t)m * N + c) = make_float2(u0, u1);
                } else if (MODE == 4) {
                    Cu[(size_t)m * N + c]     = f2tf(u0);
                    Cu[(size_t)m * N + c + 1] = f2tf(u1);
                } else if (MODE == 5) {
                    int bq = m >> 11, s = m & 2047;
                    int hh = c >> 6;
                    size_t tb = (((size_t)((bq << 4) + hh) * 32) + (s >> 6)) * 4096;
                    int jj = (s & 63) >> 3, gg = s & 7;
                    Cu[tb + k_frag_off(jj, gg, c & 63)]       = f2tf(u0);
                    Cu[tb + k_frag_off(jj, gg, (c + 1) & 63)] = f2tf(u1);
                } else {  // MODE 6
                    int bq = m >> 11, s = m & 2047;
                    int hh = c >> 6;
                    size_t tb = (((size_t)((bq << 4) + hh) * 32) + (s >> 6)) * 4096;
                    int kv = s & 63;
                    Cu[tb + v_frag_off(kv, c & 63)]       = f2tf(u0);
                    Cu[tb + v_frag_off(kv, (c + 1) & 63)] = f2tf(u1);
                }
            }
        }
    }
}

// ======== fp16 GEMM (expert W2): A fragment-tiled fp16, B transposed [N][K/2] ========
#define BSPH 36
__global__ void __launch_bounds__(256, 2) gemm_h2(
    const uint32_t* __restrict__ At, const uint32_t* __restrict__ BT,
    const float* __restrict__ bias, float* __restrict__ C,
    int N, int Kd,
    const int* __restrict__ rowidx, const float* __restrict__ roww,
    const int* __restrict__ Mcnt)
{
    extern __shared__ uint32_t sm[];
    uint32_t* As = sm;                   // [2][4096]
    uint32_t* Bs = sm + 8192;            // [2][128*BSPH]

    int Meff = *Mcnt;
    int m0 = blockIdx.y * 128;
    if (m0 >= Meff) return;
    int n0 = blockIdx.x * 128;

    int tid = threadIdx.x;
    int wid = tid >> 5, lane = tid & 31;
    int wrow = wid >> 2, wn = (wid & 3) * 32;
    int g = lane >> 2, tg = lane & 3;
    int K2 = Kd >> 1;

    uint32_t sA = (uint32_t)__cvta_generic_to_shared(As);
    uint32_t sB = (uint32_t)__cvta_generic_to_shared(Bs);

    float4 acc[4][4];
#pragma unroll
    for (int i = 0; i < 4; i++)
#pragma unroll
        for (int j = 0; j < 4; j++) acc[i][j] = make_float4(0.f, 0.f, 0.f, 0.f);

    int nk = Kd >> 6;
    size_t abase = (size_t)blockIdx.y * nk * 4096;

    {
        const uint32_t* at = At + abase;
#pragma unroll
        for (int j = 0; j < 4; j++) {
            int c = tid + j * 256;
            CPA16(sA + c * 16, at + c * 4);
        }
#pragma unroll
        for (int j = 0; j < 4; j++) {
            int c = tid + j * 256;
            int row = c >> 3, ch = c & 7;
            CPA16(sB + (row * BSPH + ch * 4) * 4, BT + (size_t)(n0 + row) * K2 + ch * 4);
        }
        CPA_COMMIT();
    }

    for (int i = 0; i < nk; i++) {
        int buf = i & 1;
        CPA_WAIT0();
        __syncthreads();
        if (i + 1 < nk) {
            int nb = buf ^ 1;
            const uint32_t* at = At + abase + (size_t)(i + 1) * 4096;
#pragma unroll
            for (int j = 0; j < 4; j++) {
                int c = tid + j * 256;
                CPA16(sA + (nb * 4096 + c * 4) * 4, at + c * 4);
            }
#pragma unroll
            for (int j = 0; j < 4; j++) {
                int c = tid + j * 256;
                int row = c >> 3, ch = c & 7;
                CPA16(sB + ((nb * 128 + row) * BSPH + ch * 4) * 4,
                      BT + (size_t)(n0 + row) * K2 + (i + 1) * 32 + ch * 4);
            }
            CPA_COMMIT();
        }

        const uint4* Ab = (const uint4*)(As + buf * 4096);
        const uint32_t* Bb = Bs + buf * 128 * BSPH;
#pragma unroll
        for (int ks = 0; ks < 4; ks++) {
            uint4 af[4];
#pragma unroll
            for (int i2 = 0; i2 < 4; i2++)
                af[i2] = Ab[(ks * 8 + wrow * 4 + i2) * 32 + lane];
            uint32_t bfr[4][2];
#pragma unroll
            for (int j = 0; j < 4; j++) {
                int n = wn + j * 8 + g;
                bfr[j][0] = Bb[n * BSPH + ks * 8 + tg];
                bfr[j][1] = Bb[n * BSPH + ks * 8 + 4 + tg];
            }
#pragma unroll
            for (int i2 = 0; i2 < 4; i2++)
#pragma unroll
                for (int j = 0; j < 4; j++)
                    mma16(acc[i2][j], (const uint32_t*)&af[i2], bfr[j]);
        }
        __syncthreads();
    }

#pragma unroll
    for (int i = 0; i < 4; i++) {
#pragma unroll
        for (int half = 0; half < 2; half++) {
            int m = m0 + wrow * 64 + i * 16 + g + half * 8;
            if (m >= Meff) continue;
            int crow = rowidx[m];
            float w = roww[m];
            float* cp = C + (size_t)crow * N;
#pragma unroll
            for (int j = 0; j < 4; j++) {
                int c = n0 + wn + j * 8 + tg * 2;
                float2 bp = *(const float2*)(bias + c);
                float u0 = (half ? acc[i][j].z : acc[i][j].x) + bp.x;
                float u1 = (half ? acc[i][j].w : acc[i][j].y) + bp.y;
                float2 old = *(float2*)(cp + c);
                old.x += w * u0; old.y += w * u1;
                *(float2*)(cp + c) = old;
            }
        }
    }
}

// ======== gathered fp16 GEMM (expert W1): A row-major pairs gathered, gelu -> tiled Ht ========
#define ASPH 36
__global__ void __launch_bounds__(256, 2) gemm_gather_h(
    const uint32_t* __restrict__ Ah, const uint32_t* __restrict__ BT,
    const float* __restrict__ bias, uint32_t* __restrict__ Ht,
    int N, int Kd,
    const int* __restrict__ rowidx, const int* __restrict__ Mcnt)
{
    extern __shared__ uint32_t sm[];
    uint32_t* As = sm;                    // [2][128*ASPH]
    uint32_t* Bs = sm + 2 * 128 * ASPH;   // [2][128*BSPH]

    int Meff = *Mcnt;
    int m0 = blockIdx.y * 128;
    if (m0 >= Meff) return;
    int n0 = blockIdx.x * 128;

    int tid = threadIdx.x;
    int wid = tid >> 5, lane = tid & 31;
    int wrow = wid >> 2, wn = (wid & 3) * 32;
    int g = lane >> 2, tg = lane & 3;
    int wm = wrow * 64;
    int K2 = Kd >> 1;

    uint32_t sA = (uint32_t)__cvta_generic_to_shared(As);
    uint32_t sB = (uint32_t)__cvta_generic_to_shared(Bs);

    int amr = tid >> 3, ack = tid & 7;
    int ga[4]; uint32_t asz[4];
#pragma unroll
    for (int j = 0; j < 4; j++) {
        int m = m0 + amr + j * 32;
        bool ok = m < Meff;
        ga[j] = ok ? rowidx[m] : 0;
        asz[j] = ok ? 16u : 0u;
    }

    float4 acc[4][4];
#pragma unroll
    for (int i = 0; i < 4; i++)
#pragma unroll
        for (int j = 0; j < 4; j++) acc[i][j] = make_float4(0.f, 0.f, 0.f, 0.f);

    int nk = Kd >> 6;

    {
#pragma unroll
        for (int j = 0; j < 4; j++) {
            int m = amr + j * 32;
            CPA16Z(sA + (m * ASPH + ack * 4) * 4, Ah + (size_t)ga[j] * K2 + ack * 4, asz[j]);
        }
#pragma unroll
        for (int j = 0; j < 4; j++) {
            int c = tid + j * 256;
            int row = c >> 3, ch = c & 7;
            CPA16(sB + (row * BSPH + ch * 4) * 4, BT + (size_t)(n0 + row) * K2 + ch * 4);
        }
        CPA_COMMIT();
    }

    for (int i = 0; i < nk; i++) {
        int buf = i & 1;
        CPA_WAIT0();
        __syncthreads();
        if (i + 1 < nk) {
            int nb = buf ^ 1;
#pragma unroll
            for (int j = 0; j < 4; j++) {
                int m = amr + j * 32;
                CPA16Z(sA + ((nb * 128 + m) * ASPH + ack * 4) * 4,
                       Ah + (size_t)ga[j] * K2 + (i + 1) * 32 + ack * 4, asz[j]);
            }
#pragma unroll
            for (int j = 0; j < 4; j++) {
                int c = tid + j * 256;
                int row = c >> 3, ch = c & 7;
                CPA16(sB + ((nb * 128 + row) * BSPH + ch * 4) * 4,
                      BT + (size_t)(n0 + row) * K2 + (i + 1) * 32 + ch * 4);
            }
            CPA_COMMIT();
        }

        const uint32_t* Ab = As + buf * 128 * ASPH;
        const uint32_t* Bb = Bs + buf * 128 * BSPH;
#pragma unroll
        for (int ks = 0; ks < 4; ks++) {
            uint32_t af[4][4];
#pragma unroll
            for (int i2 = 0; i2 < 4; i2++) {
                int r0 = wm + i2 * 16 + g, r1 = r0 + 8;
                af[i2][0] = Ab[r0 * ASPH + ks * 8 + tg];
                af[i2][1] = Ab[r1 * ASPH + ks * 8 + tg];
                af[i2][2] = Ab[r0 * ASPH + ks * 8 + 4 + tg];
                af[i2][3] = Ab[r1 * ASPH + ks * 8 + 4 + tg];
            }
            uint32_t bfr[4][2];
#pragma unroll
            for (int j = 0; j < 4; j++) {
                int n = wn + j * 8 + g;
                bfr[j][0] = Bb[n * BSPH + ks * 8 + tg];
                bfr[j][1] = Bb[n * BSPH + ks * 8 + 4 + tg];
            }
#pragma unroll
            for (int i2 = 0; i2 < 4; i2++)
#pragma unroll
                for (int j = 0; j < 4; j++)
                    mma16(acc[i2][j], af[i2], bfr[j]);
        }
        __syncthreads();
    }

    int nktH = N >> 6;
#pragma unroll
    for (int i = 0; i < 4; i++) {
#pragma unroll
        for (int half = 0; half < 2; half++) {
            int m = m0 + wm + i * 16 + g + half * 8;
            if (m >= Meff) continue;
            size_t rowtb = (size_t)(m >> 7) * nktH;
            int mloc = m & 127;
#pragma unroll
            for (int j = 0; j < 4; j++) {
                int c = n0 + wn + j * 8 + tg * 2;
                float2 bp = *(const float2*)(bias + c);
                float u0 = gelu_f((half ? acc[i][j].z : acc[i][j].x) + bp.x);
                float u1 = gelu_f((half ? acc[i][j].w : acc[i][j].y) + bp.y);
                size_t tb = (rowtb + (c >> 6)) * 4096;
                Ht[tb + a_u32_off_h(mloc, c & 63)] = f2h2(u0, u1);
            }
        }
    }
}

// ---------------- flash attention, tf32, frag-major K/V + cp.async double buffer ----------------
// bit-identical numerics to R15 (same f2tf rounding points).
#define KP 68
__global__ void __launch_bounds__(128) attn_tc2(
    const uint32_t* __restrict__ Qt, const uint32_t* __restrict__ Kf,
    const uint32_t* __restrict__ Vf, uint32_t* __restrict__ AOt)
{
    extern __shared__ uint32_t smx[];
    uint32_t* Kb = smx;            // [2][4096]
    uint32_t* Vb = smx + 8192;     // [2][4096]
    uint32_t* Ps = smx + 16384;    // [64][KP]

    int bh = blockIdx.y;
    int b = bh >> 4, h = bh & 15;
    int q0 = blockIdx.x * 64;
    int tid = threadIdx.x;
    int wid = tid >> 5, lane = tid & 31;
    int g = lane >> 2, tg = lane & 3;
    int w16 = wid * 16;
    const unsigned fullm = 0xffffffffu;

    uint32_t sKb = (uint32_t)__cvta_generic_to_shared(Kb);
    uint32_t sVb = (uint32_t)__cvta_generic_to_shared(Vb);

    // stage Q (row-major head slice) into Kb buf0, build resident fragments
#pragma unroll
    for (int j = 0; j < 8; j++) {
        int c = tid + j * 128;
        int r = c >> 4, ch = c & 15;
        CPA16(sKb + (r * 64 + ch * 4) * 4,
              Qt + (size_t)(b * Sc + q0 + r) * Dc + h * 64 + ch * 4);
    }
    CPA_COMMIT(); CPA_WAIT0();
    __syncthreads();
    uint32_t qf[8][4];
#pragma unroll
    for (int d0 = 0; d0 < 8; d0++) {
        qf[d0][0] = Kb[(w16 + g) * 64 + d0 * 8 + tg];
        qf[d0][1] = Kb[(w16 + 8 + g) * 64 + d0 * 8 + tg];
        qf[d0][2] = Kb[(w16 + g) * 64 + d0 * 8 + 4 + tg];
        qf[d0][3] = Kb[(w16 + 8 + g) * 64 + d0 * 8 + 4 + tg];
    }
    __syncthreads();

    size_t kvbase = (size_t)bh * 32 * 4096;

    // prologue: tile 0 -> buf 0
#pragma unroll
    for (int j = 0; j < 8; j++) {
        int c = tid + j * 128;
        CPA16(sKb + c * 16, Kf + kvbase + c * 4);
        CPA16(sVb + c * 16, Vf + kvbase + c * 4);
    }
    CPA_COMMIT();

    float m0r = -1e30f, m1r = -1e30f;
    float l0r = 0.f, l1r = 0.f;
    float4 of[8];
#pragma unroll
    for (int j = 0; j < 8; j++) of[j] = make_float4(0.f, 0.f, 0.f, 0.f);

    for (int i = 0; i < 32; i++) {
        int buf = i & 1;
        if (i + 1 < 32) {
            int nb = buf ^ 1;
            size_t tb = kvbase + (size_t)(i + 1) * 4096;
#pragma unroll
            for (int j = 0; j < 8; j++) {
                int c = tid + j * 128;
                CPA16(sKb + (nb * 4096 + c * 4) * 4, Kf + tb + c * 4);
                CPA16(sVb + (nb * 4096 + c * 4) * 4, Vf + tb + c * 4);
            }
            CPA_COMMIT();
            CPA_WAIT1();
        } else {
            CPA_WAIT0();
        }
        __syncthreads();

        // S = Q @ K^T (packed B-fragments: one LDS.128 -> 2 mma8)
        float4 sa[8];
#pragma unroll
        for (int j = 0; j < 8; j++) sa[j] = make_float4(0.f, 0.f, 0.f, 0.f);
        const uint4* KbU = (const uint4*)(Kb + buf * 4096);
#pragma unroll
        for (int p = 0; p < 4; p++) {
#pragma unroll
            for (int j = 0; j < 8; j++) {
                uint4 kb = KbU[(j * 4 + p) * 32 + lane];
                mma8(sa[j], qf[2 * p],     &kb.x);
                mma8(sa[j], qf[2 * p + 1], &kb.z);
            }
        }

        // online softmax (identical to R15)
        float t0 = -1e30f, t1 = -1e30f;
#pragma unroll
        for (int j = 0; j < 8; j++) {
            sa[j].x *= 0.125f; sa[j].y *= 0.125f; sa[j].z *= 0.125f; sa[j].w *= 0.125f;
            t0 = fmaxf(t0, fmaxf(sa[j].x, sa[j].y));
            t1 = fmaxf(t1, fmaxf(sa[j].z, sa[j].w));
        }
        t0 = fmaxf(t0, __shfl_xor_sync(fullm, t0, 1));
        t0 = fmaxf(t0, __shfl_xor_sync(fullm, t0, 2));
        t1 = fmaxf(t1, __shfl_xor_sync(fullm, t1, 1));
        t1 = fmaxf(t1, __shfl_xor_sync(fullm, t1, 2));
        float mn0 = fmaxf(m0r, t0), mn1 = fmaxf(m1r, t1);
        float al0 = __expf(m0r - mn0), al1 = __expf(m1r - mn1);
        float rs0 = 0.f, rs1 = 0.f;
#pragma unroll
        for (int j = 0; j < 8; j++) {
            sa[j].x = __expf(sa[j].x - mn0); sa[j].y = __expf(sa[j].y - mn0);
            sa[j].z = __expf(sa[j].z - mn1); sa[j].w = __expf(sa[j].w - mn1);
            rs0 += sa[j].x + sa[j].y; rs1 += sa[j].z + sa[j].w;
        }
        rs0 += __shfl_xor_sync(fullm, rs0, 1); rs0 += __shfl_xor_sync(fullm, rs0, 2);
        rs1 += __shfl_xor_sync(fullm, rs1, 1); rs1 += __shfl_xor_sync(fullm, rs1, 2);
        l0r = l0r * al0 + rs0; l1r = l1r * al1 + rs1;
        m0r = mn0; m1r = mn1;
#pragma unroll
        for (int j = 0; j < 8; j++) {
            of[j].x *= al0; of[j].y *= al0; of[j].z *= al1; of[j].w *= al1;
        }

        // re-fragment P (tf32) through warp-private smem (R15 scheme)
#pragma unroll
        for (int j = 0; j < 8; j++) {
            int col = j * 8 + tg * 2;
            Ps[(w16 + g) * KP + col]     = f2tf(sa[j].x);
            Ps[(w16 + g) * KP + col + 1] = f2tf(sa[j].y);
            Ps[(w16 + 8 + g) * KP + col]     = f2tf(sa[j].z);
            Ps[(w16 + 8 + g) * KP + col + 1] = f2tf(sa[j].w);
        }
        __syncwarp();

        // O += P @ V (packed V B-fragments)
        const uint4* VbU = (const uint4*)(Vb + buf * 4096);
#pragma unroll
        for (int q = 0; q < 4; q++) {
            uint32_t af0[4], af1[4];
            int k0 = 2 * q;
            af0[0] = Ps[(w16 + g) * KP + k0 * 8 + tg];
            af0[1] = Ps[(w16 + 8 + g) * KP + k0 * 8 + tg];
            af0[2] = Ps[(w16 + g) * KP + k0 * 8 + 4 + tg];
            af0[3] = Ps[(w16 + 8 + g) * KP + k0 * 8 + 4 + tg];
            af1[0] = Ps[(w16 + g) * KP + (k0 + 1) * 8 + tg];
            af1[1] = Ps[(w16 + 8 + g) * KP + (k0 + 1) * 8 + tg];
            af1[2] = Ps[(w16 + g) * KP + (k0 + 1) * 8 + 4 + tg];
            af1[3] = Ps[(w16 + 8 + g) * KP + (k0 + 1) * 8 + 4 + tg];
#pragma unroll
            for (int j = 0; j < 8; j++) {
                uint4 v = VbU[(j * 4 + q) * 32 + lane];
                mma8(of[j], af0, &v.x);
                mma8(of[j], af1, &v.z);
            }
        }
        __syncthreads();
    }

    // epilogue -> tiled-fragment tf32 AO (identical to R15)
    float inv0 = 1.f / l0r, inv1 = 1.f / l1r;
    int mg0 = b * Sc + q0 + w16 + g;
    int mg1 = mg0 + 8;
    size_t rtb0 = (size_t)(mg0 >> 7) * 32;
    size_t rtb1 = (size_t)(mg1 >> 7) * 32;
    int ml0 = mg0 & 127, ml1 = mg1 & 127;
#pragma unroll
    for (int j = 0; j < 8; j++) {
        int col = h * 64 + j * 8 + tg * 2;
        size_t tb0 = (rtb0 + (col >> 5)) * 4096;
        size_t tb1 = (rtb1 + (col >> 5)) * 4096;
        AOt[tb0 + a_elem_off(ml0, col & 31)]       = f2tf(of[j].x * inv0);
        AOt[tb0 + a_elem_off(ml0, (col + 1) & 31)] = f2tf(of[j].y * inv0);
        AOt[tb1 + a_elem_off(ml1, col & 31)]       = f2tf(of[j].z * inv1);
        AOt[tb1 + a_elem_off(ml1, (col + 1) & 31)] = f2tf(of[j].w * inv1);
    }
}

// ---------------- residual + layernorm (optional fp16-pair copy) ----------------
__global__ void __launch_bounds__(256) add_ln_kernel(
    const float* __restrict__ xin, const float* __restrict__ res,
    const float* __restrict__ g, const float* __restrict__ bta,
    float* __restrict__ out, uint32_t* __restrict__ outh)
{
    int t = blockIdx.x;
    int tid = threadIdx.x;
    const float4 xv = ((const float4*)(xin + (size_t)t * Dc))[tid];
    const float4 rv = ((const float4*)(res + (size_t)t * Dc))[tid];
    float v[4] = {xv.x + rv.x, xv.y + rv.y, xv.z + rv.z, xv.w + rv.w};
    float s  = v[0] + v[1] + v[2] + v[3];
    float sq = v[0]*v[0] + v[1]*v[1] + v[2]*v[2] + v[3]*v[3];
#pragma unroll
    for (int off = 16; off; off >>= 1) {
        s  += __shfl_xor_sync(0xffffffffu, s, off);
        sq += __shfl_xor_sync(0xffffffffu, sq, off);
    }
    __shared__ float ss[8], qq[8];
    __shared__ float smu, srstd;
    int wid = tid >> 5;
    if ((tid & 31) == 0) { ss[wid] = s; qq[wid] = sq; }
    __syncthreads();
    if (tid == 0) {
        float ts = 0.f, tq = 0.f;
#pragma unroll
        for (int i = 0; i < 8; i++) { ts += ss[i]; tq += qq[i]; }
        float mu = ts / (float)Dc;
        float var = tq / (float)Dc - mu * mu;
        smu = mu; srstd = rsqrtf(var + 1e-5f);
    }
    __syncthreads();
    float mu = smu, rstd = srstd;
    float4 g4 = ((const float4*)g)[tid];
    float4 b4 = ((const float4*)bta)[tid];
    float4 o4;
    o4.x = (v[0]-mu)*rstd*g4.x + b4.x;
    o4.y = (v[1]-mu)*rstd*g4.y + b4.y;
    o4.z = (v[2]-mu)*rstd*g4.z + b4.z;
    o4.w = (v[3]-mu)*rstd*g4.w + b4.w;
    ((float4*)(out + (size_t)t * Dc))[tid] = o4;
    if (outh)
        ((uint2*)(outh + (size_t)t * (Dc / 2)))[tid] =
            make_uint2(f2h2(o4.x, o4.y), f2h2(o4.z, o4.w));
}

// ---------------- gate ----------------
__global__ void __launch_bounds__(256) gate_kernel(
    const float* __restrict__ x1, const float* __restrict__ gW,
    const float* __restrict__ gb)
{
    int t = blockIdx.x;
    int tid = threadIdx.x;
    float part[Ec];
#pragma unroll
    for (int e = 0; e < Ec; e++) part[e] = 0.f;
    const float* xr = x1 + (size_t)t * Dc;
    for (int d = tid; d < Dc; d += 256) {
        float xv = xr[d];
        const float* wr = gW + d * Ec;
#pragma unroll
        for (int e = 0; e < Ec; e++) part[e] += xv * wr[e];
    }
    __shared__ float sm[Ec][264];
#pragma unroll
    for (int e = 0; e < Ec; e++) sm[e][tid] = part[e];
    __syncthreads();
    for (int off = 128; off; off >>= 1) {
        if (tid < off) {
#pragma unroll
            for (int e = 0; e < Ec; e++) sm[e][tid] += sm[e][tid + off];
        }
        __syncthreads();
    }
    if (tid == 0) {
        float lg[Ec], sc[Ec];
        float m = -1e30f;
#pragma unroll
        for (int e = 0; e < Ec; e++) { lg[e] = sm[e][0] + gb[e]; m = fmaxf(m, lg[e]); }
        float sum = 0.f;
#pragma unroll
        for (int e = 0; e < Ec; e++) { sc[e] = expf(lg[e] - m); sum += sc[e]; }
        float inv = 1.f / sum;
#pragma unroll
        for (int e = 0; e < Ec; e++) { sc[e] *= inv; g_scores[t * Ec + e] = sc[e]; }
        int a1 = 0;
#pragma unroll
        for (int e = 1; e < Ec; e++) if (sc[e] > sc[a1]) a1 = e;
        int a2 = (a1 == 0) ? 1 : 0;
#pragma unroll
        for (int e = 0; e < Ec; e++) if (e != a1 && sc[e] > sc[a2]) a2 = e;
        float ws = sc[a1] + sc[a2];
        float w1 = sc[a1] / ws, w2 = sc[a2] / ws;
        int p1 = atomicAdd(&g_cnt[a1], 1);
        g_eidx[a1 * Tc + p1] = t; g_ewgt[a1 * Tc + p1] = w1;
        int p2 = atomicAdd(&g_cnt[a2], 1);
        g_eidx[a2 * Tc + p2] = t; g_ewgt[a2 * Tc + p2] = w2;
    }
}

// ---------------- aux loss ----------------
__global__ void __launch_bounds__(256) aux_kernel(float* __restrict__ out)
{
    int tid = threadIdx.x;
    float part[Ec];
#pragma unroll
    for (int e = 0; e < Ec; e++) part[e] = 0.f;
    for (int t = tid; t < Tc; t += 256) {
#pragma unroll
        for (int e = 0; e < Ec; e++) part[e] += g_scores[t * Ec + e];
    }
    __shared__ float sm[Ec][264];
#pragma unroll
    for (int e = 0; e < Ec; e++) sm[e][tid] = part[e];
    __syncthreads();
    for (int off = 128; off; off >>= 1) {
        if (tid < off) {
#pragma unroll
            for (int e = 0; e < Ec; e++) sm[e][tid] += sm[e][tid + off];
        }
        __syncthreads();
    }
    if (tid == 0) {
        float aux = 0.f;
#pragma unroll
        for (int e = 0; e < Ec; e++) {
            float ef = (float)g_cnt[e] / (float)(Tc * Kc);
            float rw = sm[e][0] / (float)Tc;
            aux += ef * rw;
        }
        out[0] = aux * (float)Ec;
    }
}

// ---------------- state reset ----------------
__global__ void zero_cnt_kernel() {
    if (threadIdx.x < Ec) g_cnt[threadIdx.x] = 0;
}
__global__ void zero_moe_kernel() {
    size_t i = ((size_t)blockIdx.x * 256 + threadIdx.x) * 4;
    *(float4*)(g_moe + i) = make_float4(0.f, 0.f, 0.f, 0.f);
}

// ---------------- launch ----------------
extern "C" void kernel_launch(void* const* d_in, const int* in_sizes, int n_in,
                              void* d_out, int out_size)
{
    (void)in_sizes; (void)n_in; (void)out_size;
    const float* x     = (const float*)d_in[0];
    const float* Wq    = (const float*)d_in[1];
    const float* bq    = (const float*)d_in[2];
    const float* Wk    = (const float*)d_in[3];
    const float* bk    = (const float*)d_in[4];
    const float* Wv    = (const float*)d_in[5];
    const float* bv    = (const float*)d_in[6];
    const float* Wo    = (const float*)d_in[7];
    const float* bo    = (const float*)d_in[8];
    const float* g1    = (const float*)d_in[9];
    const float* beta1 = (const float*)d_in[10];
    const float* gateW = (const float*)d_in[11];
    const float* gateb = (const float*)d_in[12];
    const float* eW1   = (const float*)d_in[13];
    const float* eb1   = (const float*)d_in[14];
    const float* eW2   = (const float*)d_in[15];
    const float* eb2   = (const float*)d_in[16];
    const float* g2    = (const float*)d_in[17];
    const float* beta2 = (const float*)d_in[18];
    float* out = (float*)d_out;

    float *pP, *pX1, *pMoe, *pWgt;
    uint32_t *pxt, *pWt, *pQt, *pKf, *pVf, *pAOt, *pX1h, *pHt, *peW1T, *peW2T;
    int *pCnt, *pIdx;
    cudaGetSymbolAddress((void**)&pxt,   g_xt);
    cudaGetSymbolAddress((void**)&pWt,   g_Wt);
    cudaGetSymbolAddress((void**)&pQt,   g_Qt);
    cudaGetSymbolAddress((void**)&pKf,   g_Kf);
    cudaGetSymbolAddress((void**)&pVf,   g_Vf);
    cudaGetSymbolAddress((void**)&pAOt,  g_AOt);
    cudaGetSymbolAddress((void**)&pP,    g_P);
    cudaGetSymbolAddress((void**)&pX1,   g_X1);
    cudaGetSymbolAddress((void**)&pX1h,  g_X1h);
    cudaGetSymbolAddress((void**)&pMoe,  g_moe);
    cudaGetSymbolAddress((void**)&pHt,   g_Ht);
    cudaGetSymbolAddress((void**)&peW1T, g_eW1T);
    cudaGetSymbolAddress((void**)&peW2T, g_eW2T);
    cudaGetSymbolAddress((void**)&pCnt,  g_cnt);
    cudaGetSymbolAddress((void**)&pIdx,  g_eidx);
    cudaGetSymbolAddress((void**)&pWgt,  g_ewgt);

    const int attn_smem = (4 * 4096 + 64 * KP) * 4;               // 82944
    const int gA_smem   = (2 * 4096 + 2 * 32 * BSP) * 4;          // 67584
    const int gH_smem   = (2 * 4096 + 2 * 128 * BSPH) * 4;        // 69632
    const int gG_smem   = (2 * 128 * ASPH + 2 * 128 * BSPH) * 4;  // 73728
    cudaFuncSetAttribute(attn_tc2, cudaFuncAttributeMaxDynamicSharedMemorySize, attn_smem);
    cudaFuncSetAttribute(gemm_tcA<0>, cudaFuncAttributeMaxDynamicSharedMemorySize, gA_smem);
    cudaFuncSetAttribute(gemm_tcA<4>, cudaFuncAttributeMaxDynamicSharedMemorySize, gA_smem);
    cudaFuncSetAttribute(gemm_tcA<5>, cudaFuncAttributeMaxDynamicSharedMemorySize, gA_smem);
    cudaFuncSetAttribute(gemm_tcA<6>, cudaFuncAttributeMaxDynamicSharedMemorySize, gA_smem);
    cudaFuncSetAttribute(gemm_h2, cudaFuncAttributeMaxDynamicSharedMemorySize, gH_smem);
    cudaFuncSetAttribute(gemm_gather_h, cudaFuncAttributeMaxDynamicSharedMemorySize, gG_smem);

    zero_cnt_kernel<<<1, 32>>>();
    zero_moe_kernel<<<(Tc * Dc) / 1024, 256>>>();

    // conversions: tf32 for pre-routing, fp16 for experts
    conv_tiled<<<dim3(Dc / 32, Tc / 128), 256>>>(x, pxt, Dc);
    conv_plain<<<512, 256>>>(Wq, pWt + 0 * (size_t)Dc * Dc, (size_t)Dc * Dc / 4);
    conv_plain<<<512, 256>>>(Wk, pWt + 1 * (size_t)Dc * Dc, (size_t)Dc * Dc / 4);
    conv_plain<<<512, 256>>>(Wv, pWt + 2 * (size_t)Dc * Dc, (size_t)Dc * Dc / 4);
    conv_plain<<<512, 256>>>(Wo, pWt + 3 * (size_t)Dc * Dc, (size_t)Dc * Dc / 4);
    conv_wT<<<dim3(Fc / 64, Dc / 64, Ec), 256>>>(eW1, peW1T, Dc, Fc);
    conv_wT<<<dim3(Dc / 64, Fc / 64, Ec), 256>>>(eW2, peW2T, Fc, Dc);

    dim3 gD(Dc / 128, Tc / 128);   // (8, 64)
    gemm_tcA<4><<<gD, 256, gA_smem>>>(pxt, pWt + 0 * (size_t)Dc * Dc, bq, nullptr, pQt, Dc, Dc, Dc / 32);
    gemm_tcA<5><<<gD, 256, gA_smem>>>(pxt, pWt + 1 * (size_t)Dc * Dc, bk, nullptr, pKf, Dc, Dc, Dc / 32);
    gemm_tcA<6><<<gD, 256, gA_smem>>>(pxt, pWt + 2 * (size_t)Dc * Dc, bv, nullptr, pVf, Dc, Dc, Dc / 32);

    attn_tc2<<<dim3(Sc / 64, Bc * Hc), 128, attn_smem>>>(pQt, pKf, pVf, pAOt);

    gemm_tcA<0><<<gD, 256, gA_smem>>>(pAOt, pWt + 3 * (size_t)Dc * Dc, bo, pP, nullptr, Dc, Dc, Dc / 32);
    add_ln_kernel<<<Tc, 256>>>(x, pP, g1, beta1, pX1, pX1h);

    gate_kernel<<<Tc, 256>>>(pX1, gateW, gateb);

    dim3 gF(Fc / 128, Tc / 128);   // (32, 64)
    for (int e = 0; e < Ec; e++) {
        gemm_gather_h<<<gF, 256, gG_smem>>>(pX1h, peW1T + (size_t)e * Dc * Fc / 2, eb1 + e * Fc,
                                            pHt, Fc, Dc, pIdx + e * Tc, pCnt + e);
        gemm_h2<<<gD, 256, gH_smem>>>(pHt, peW2T + (size_t)e * Fc * Dc / 2, eb2 + e * Dc,
                                      pMoe, Dc, Fc,
                                      pIdx + e * Tc, pWgt + e * Tc, pCnt + e);
    }

    add_ln_kernel<<<Tc, 256>>>(pX1, pMoe, g2, beta2, out, nullptr);
    aux_kernel<<<1, 256>>>(out + (size_t)Tc * Dc);
}